// round 6
// baseline (speedup 1.0000x reference)
#include <cuda_runtime.h>
#include <cuda_bf16.h>
#include <math.h>
#include <stdint.h>

#define T_STEPS 1024
#define BATCH   64
#define INDIM   512
#define HID     1024
#define G4      4096

#define NBLK 128

// recurrent kernel geometry
#define CHUNKS  16
#define CKROWS  64                   // k rows per chunk
#define AROWB   144                  // 72 bf16 per k-row (64 b + 8 pad)
#define APLANE  (CKROWS * AROWB)     // 9216 bytes
#define ABUF    (2 * APLANE)         // hi+lo = 18432
#define NBUF    4
#define WROWB   2064                 // 1032 bf16 per W row (1024 + 8 pad)
#define WPLANE  (32 * WROWB)         // 66048
#define SM_W    0
#define SM_AB   (2 * WPLANE)         // 132096
#define SM_MB   (SM_AB + NBUF * ABUF)  // 205824
#define SM_ST   (SM_MB + 64)           // 205888 ; 16 rows x 136B staging
#define R_SMEM  (SM_ST + 16 * 136)     // 208064

// ---------------- device scratch (static) ----------------
__device__ float          g_xproj[(size_t)T_STEPS * BATCH * G4];   // [t][b][j*4+gate]
__device__ __nv_bfloat16  g_xhi[(size_t)T_STEPS * BATCH * INDIM];
__device__ __nv_bfloat16  g_xlo[(size_t)T_STEPS * BATCH * INDIM];
__device__ __nv_bfloat16  g_wihhi[(size_t)G4 * INDIM];
__device__ __nv_bfloat16  g_wihlo[(size_t)G4 * INDIM];
__device__ __nv_bfloat16  g_hT[2][2][HID][72];   // [buf][hi/lo][k][b(+pad)]
__device__ int            g_flags[NBLK];

// ---------------- helpers ----------------
__device__ __forceinline__ uint32_t smem_u32(const void* p) {
    uint32_t a;
    asm("{ .reg .u64 t; cvta.to.shared.u64 t, %1; cvt.u32.u64 %0, t; }" : "=r"(a) : "l"(p));
    return a;
}

#define LDSM_X4(r0,r1,r2,r3,addr) \
    asm volatile("ldmatrix.sync.aligned.m8n8.x4.shared.b16 {%0,%1,%2,%3}, [%4];" \
                 : "=r"(r0), "=r"(r1), "=r"(r2), "=r"(r3) : "r"(addr))

#define LDSM_X4T(r0,r1,r2,r3,addr) \
    asm volatile("ldmatrix.sync.aligned.m8n8.x4.trans.shared.b16 {%0,%1,%2,%3}, [%4];" \
                 : "=r"(r0), "=r"(r1), "=r"(r2), "=r"(r3) : "r"(addr))

__device__ __forceinline__ void mma_bf16(float& d0, float& d1, float& d2, float& d3,
                                         uint32_t a0, uint32_t a1, uint32_t a2, uint32_t a3,
                                         uint32_t b0, uint32_t b1) {
    asm volatile(
        "mma.sync.aligned.m16n8k16.row.col.f32.bf16.bf16.f32 "
        "{%0,%1,%2,%3}, {%4,%5,%6,%7}, {%8,%9}, {%0,%1,%2,%3};"
        : "+f"(d0), "+f"(d1), "+f"(d2), "+f"(d3)
        : "r"(a0), "r"(a1), "r"(a2), "r"(a3), "r"(b0), "r"(b1));
}

#define MBARRIER_INIT(mbar, count) \
    asm volatile("mbarrier.init.shared.b64 [%0], %1;" :: "r"((uint32_t)(mbar)), "r"((uint32_t)(count)) : "memory")

#define MBARRIER_EXPECT_TX(mbar, tx) \
    asm volatile("mbarrier.arrive.expect_tx.shared.b64 _, [%0], %1;" \
                 :: "r"((uint32_t)(mbar)), "r"((uint32_t)(tx)) : "memory")

#define MBARRIER_WAIT_PARITY(mbar_smem_addr, phase_parity) do { \
    uint32_t _mbar = (uint32_t)(mbar_smem_addr); \
    uint32_t _parity = (uint32_t)(phase_parity); \
    uint32_t _done; \
    asm volatile( \
        "{\n\t.reg .pred p;\n\t" \
        "mbarrier.try_wait.parity.acquire.cta.shared::cta.b64 p, [%1], %2;\n\t" \
        "selp.b32 %0, 1, 0, p;\n\t}" \
        : "=r"(_done) : "r"(_mbar), "r"(_parity) : "memory"); \
    if (!_done) { \
        asm volatile( \
            "{\n\t.reg .pred P1;\n\t" \
            "WAIT_LOOP_%=:\n\t" \
            "mbarrier.try_wait.parity.acquire.cta.shared::cta.b64 P1, [%0], %1, 0x989680;\n\t" \
            "@P1 bra.uni WAIT_DONE_%=;\n\t" \
            "bra.uni WAIT_LOOP_%=;\n\t" \
            "WAIT_DONE_%=:\n\t}" \
            :: "r"(_mbar), "r"(_parity) : "memory"); \
    } \
} while(0)

__device__ __forceinline__ void bulk_g2s(uint32_t dst, const void* src,
                                         uint32_t bytes, uint32_t mbar) {
    uint64_t gsrc;
    asm("cvta.to.global.u64 %0, %1;" : "=l"(gsrc) : "l"(src));
    asm volatile(
        "cp.async.bulk.shared::cluster.global.mbarrier::complete_tx::bytes [%0], [%1], %2, [%3];"
        :: "r"(dst), "l"(gsrc), "r"(bytes), "r"(mbar) : "memory");
}

__device__ __forceinline__ void cp16(uint32_t dst, const void* src) {
    asm volatile("cp.async.cg.shared.global [%0], [%1], 16;" :: "r"(dst), "l"(src) : "memory");
}
#define CP_COMMIT() asm volatile("cp.async.commit_group;" ::: "memory")
#define CP_WAIT(n)  asm volatile("cp.async.wait_group %0;" :: "n"(n) : "memory")

// fp32x4 -> packed bf16 hi (uint2) and lo residual (uint2)
__device__ __forceinline__ void split4(float4 v, uint2& hip, uint2& lop) {
    __nv_bfloat16 hx = __float2bfloat16_rn(v.x);
    __nv_bfloat16 hy = __float2bfloat16_rn(v.y);
    __nv_bfloat16 hz = __float2bfloat16_rn(v.z);
    __nv_bfloat16 hw = __float2bfloat16_rn(v.w);
    __nv_bfloat162 p0 = __halves2bfloat162(hx, hy);
    __nv_bfloat162 p1 = __halves2bfloat162(hz, hw);
    hip.x = *reinterpret_cast<unsigned*>(&p0);
    hip.y = *reinterpret_cast<unsigned*>(&p1);
    __nv_bfloat162 q0 = __floats2bfloat162_rn(v.x - __bfloat162float(hx),
                                              v.y - __bfloat162float(hy));
    __nv_bfloat162 q1 = __floats2bfloat162_rn(v.z - __bfloat162float(hz),
                                              v.w - __bfloat162float(hw));
    lop.x = *reinterpret_cast<unsigned*>(&q0);
    lop.y = *reinterpret_cast<unsigned*>(&q1);
}

__device__ __forceinline__ float sigmoidf_(float x) { return 1.0f / (1.0f + __expf(-x)); }

// ================= split pass =================
__global__ __launch_bounds__(256) void split_inputs(
    const float* __restrict__ x,
    const float* __restrict__ wih,
    const float* __restrict__ h0)
{
    if (blockIdx.x == 0 && threadIdx.x < NBLK) g_flags[threadIdx.x] = 0;

    const size_t NX  = (size_t)T_STEPS * BATCH * INDIM / 4;
    const size_t NW  = (size_t)G4 * INDIM / 4;
    const size_t NH0 = (size_t)BATCH * HID / 4;
    const size_t total = NX + NW + NH0;
    for (size_t i = (size_t)blockIdx.x * blockDim.x + threadIdx.x;
         i < total; i += (size_t)gridDim.x * blockDim.x) {
        if (i < NX) {
            float4 v = ((const float4*)x)[i];
            uint2 h, l; split4(v, h, l);
            ((uint2*)g_xhi)[i] = h;
            ((uint2*)g_xlo)[i] = l;
        } else if (i < NX + NW) {
            size_t k = i - NX;
            float4 v = ((const float4*)wih)[k];
            uint2 h, l; split4(v, h, l);
            ((uint2*)g_wihhi)[k] = h;
            ((uint2*)g_wihlo)[k] = l;
        } else {
            size_t e4 = i - NX - NW;
            size_t e  = e4 * 4;
            int b = (int)(e >> 10);
            int k = (int)(e & 1023);
            float4 v = ((const float4*)h0)[e4];
            float vv[4] = {v.x, v.y, v.z, v.w};
#pragma unroll
            for (int q = 0; q < 4; q++) {
                __nv_bfloat16 hi = __float2bfloat16_rn(vv[q]);
                __nv_bfloat16 lo = __float2bfloat16_rn(vv[q] - __bfloat162float(hi));
                g_hT[0][0][k + q][b] = hi;
                g_hT[0][1][k + q][b] = lo;
            }
        }
    }
}

// ================= x_proj GEMM (cp.async-pipelined bf16-split HMMA) =================
#define XP_ROWB 144
#define XP_TILE (128 * XP_ROWB)
#define XP_BUF  (4 * XP_TILE)
#define XP_SMEM (2 * XP_BUF)

__global__ __launch_bounds__(256) void xproj_mma(
    const float* __restrict__ bih,
    const float* __restrict__ bhh)
{
    extern __shared__ char smem[];
    const uint32_t sb = smem_u32(smem);
    const int tid  = threadIdx.x;
    const int lane = tid & 31;
    const int w    = tid >> 5;
    const int wm   = w & 1;
    const int wn   = w >> 1;
    const int jb   = blockIdx.x * 32;
    const size_t mb = (size_t)blockIdx.y * 128;

    float acc[4][4][4];
#pragma unroll
    for (int a = 0; a < 4; a++)
#pragma unroll
        for (int b = 0; b < 4; b++)
#pragma unroll
            for (int c = 0; c < 4; c++) acc[a][b][c] = 0.f;

    const int a_row = wm * 64 + (lane & 7) + ((lane >> 3) & 1) * 8;
    const int a_k8  = (lane >> 4) * 8;
    const int b_row = wn * 32 + (lane & 7) + (lane >> 4) * 8;
    const int b_k8  = ((lane >> 3) & 1) * 8;

    // per-thread staging constants
    int st_row[4], st_c[4], st_wrow[4];
#pragma unroll
    for (int q = 0; q < 4; q++) {
        int s = tid * 4 + q;
        st_row[q]  = s >> 3;
        st_c[q]    = s & 7;
        st_wrow[q] = (st_row[q] & 3) * HID + jb + (st_row[q] >> 2);
    }

    // stage chunk kb into buffer buf
    auto stage = [&](int kb, int buf) {
        uint32_t base = sb + buf * XP_BUF;
#pragma unroll
        for (int q = 0; q < 4; q++) {
            size_t gk = (size_t)kb * 64 + st_c[q] * 8;
            uint32_t off = st_row[q] * XP_ROWB + st_c[q] * 16;
            cp16(base + 0 * XP_TILE + off, &g_xhi[(mb + st_row[q]) * INDIM + gk]);
            cp16(base + 1 * XP_TILE + off, &g_xlo[(mb + st_row[q]) * INDIM + gk]);
            cp16(base + 2 * XP_TILE + off, &g_wihhi[(size_t)st_wrow[q] * INDIM + gk]);
            cp16(base + 3 * XP_TILE + off, &g_wihlo[(size_t)st_wrow[q] * INDIM + gk]);
        }
        CP_COMMIT();
    };

    stage(0, 0);

    for (int kb = 0; kb < 8; kb++) {
        const int buf = kb & 1;
        if (kb < 7) stage(kb + 1, buf ^ 1);
        if (kb < 7) { CP_WAIT(1); } else { CP_WAIT(0); }
        __syncthreads();

        const uint32_t aHi = sb + buf * XP_BUF;
        const uint32_t aLo = aHi + XP_TILE;
        const uint32_t bHi = aHi + 2 * XP_TILE;
        const uint32_t bLo = aHi + 3 * XP_TILE;

#pragma unroll
        for (int s = 0; s < 4; s++) {
            uint32_t bh[8], bl[8];
#pragma unroll
            for (int p = 0; p < 2; p++) {
                uint32_t off = (b_row + p * 16) * XP_ROWB + (s * 16 + b_k8) * 2;
                LDSM_X4(bh[p*4+0], bh[p*4+1], bh[p*4+2], bh[p*4+3], bHi + off);
                LDSM_X4(bl[p*4+0], bl[p*4+1], bl[p*4+2], bl[p*4+3], bLo + off);
            }
#pragma unroll
            for (int mt = 0; mt < 4; mt++) {
                uint32_t off = (a_row + mt * 16) * XP_ROWB + (s * 16 + a_k8) * 2;
                uint32_t ah0, ah1, ah2, ah3, al0, al1, al2, al3;
                LDSM_X4(ah0, ah1, ah2, ah3, aHi + off);
                LDSM_X4(al0, al1, al2, al3, aLo + off);
#pragma unroll
                for (int nt = 0; nt < 4; nt++) {
                    float* d = acc[mt][nt];
                    mma_bf16(d[0], d[1], d[2], d[3], ah0, ah1, ah2, ah3, bh[nt*2], bh[nt*2+1]);
                    mma_bf16(d[0], d[1], d[2], d[3], ah0, ah1, ah2, ah3, bl[nt*2], bl[nt*2+1]);
                    mma_bf16(d[0], d[1], d[2], d[3], al0, al1, al2, al3, bh[nt*2], bh[nt*2+1]);
                }
            }
        }
        __syncthreads();
    }

    const int colq = (lane & 3) * 2;
#pragma unroll
    for (int nt = 0; nt < 4; nt++) {
        int nloc = wn * 32 + nt * 8 + colq;
        int g0 = nloc & 3,        j0 = jb + (nloc >> 2);
        int g1 = (nloc + 1) & 3,  j1 = jb + ((nloc + 1) >> 2);
        float bb0 = bih[g0 * HID + j0] + bhh[g0 * HID + j0];
        float bb1 = bih[g1 * HID + j1] + bhh[g1 * HID + j1];
#pragma unroll
        for (int mt = 0; mt < 4; mt++) {
            size_t r0 = mb + wm * 64 + mt * 16 + (lane >> 2);
            float2 v0 = make_float2(acc[mt][nt][0] + bb0, acc[mt][nt][1] + bb1);
            float2 v1 = make_float2(acc[mt][nt][2] + bb0, acc[mt][nt][3] + bb1);
            *(float2*)&g_xproj[r0 * G4 + jb * 4 + nloc]       = v0;
            *(float2*)&g_xproj[(r0 + 8) * G4 + jb * 4 + nloc] = v1;
        }
    }
}

// ================= persistent recurrent kernel (4-deep bulk pipeline) =================
__global__ __launch_bounds__(256, 1) void lstm_rec_tma(
    const float* __restrict__ c0in,
    const float* __restrict__ whh,
    float* __restrict__ out, int out_size)
{
    extern __shared__ char smem[];
    const uint32_t sb = smem_u32(smem);
    const int tid  = threadIdx.x;
    const int lane = tid & 31;
    const int w    = tid >> 5;
    const int mt   = w & 3;
    const int nh   = w >> 2;
    const int blk  = blockIdx.x;
    const int hb   = blk * 8;

    if (tid == 0) {
#pragma unroll
        for (int i = 0; i < NBUF; i++) MBARRIER_INIT(sb + SM_MB + i * 8, 1);
    }
    asm volatile("fence.proxy.async.shared::cta;" ::: "memory");
    __syncthreads();

    // one-time: W slice -> smem (gate-interleaved rows), hi+lo
    for (int it = 0; it < 32; it++) {
        int e4 = it * 256 + tid;
        int n  = e4 >> 8;
        int kf = (e4 & 255) * 4;
        int nh_ = n >> 4, r = n & 15;
        int nt = r >> 3, q = (r & 7) >> 1, low = r & 1;
        int gate = nt * 2 + low, j = 4 * nh_ + q;
        float4 v = *(const float4*)&whh[(size_t)(gate * HID + hb + j) * HID + kf];
        uint2 hp, lp; split4(v, hp, lp);
        *(uint2*)(smem + SM_W + n * WROWB + kf * 2) = hp;
        *(uint2*)(smem + SM_W + WPLANE + n * WROWB + kf * 2) = lp;
    }
    __syncthreads();

    const uint32_t aK  = (lane & 7) + ((lane >> 4) << 3);
    const uint32_t aMb = (uint32_t)(mt * 16 + ((lane >> 3) & 1) * 8) * 2;
    const uint32_t bRowOff = (uint32_t)(nh * 16 + (lane & 7) + ((lane >> 4) << 3)) * WROWB;
    const uint32_t bK8 = ((lane >> 3) & 1) * 8;

    const int b0  = mt * 16 + (lane >> 2);
    const int b1  = b0 + 8;
    const int jloc = 4 * nh + (lane & 3);
    const int col = hb + jloc;

    float c0r = c0in[b0 * HID + col];
    float c1r = c0in[b1 * HID + col];
    int ph[NBUF] = {0, 0, 0, 0};

    for (int t = 0; t < T_STEPS; t++) {
        const __nv_bfloat16* hsrc = &g_hT[t & 1][0][0][0];   // hi; lo at +HID*72

        if (tid == 0) {
#pragma unroll
            for (int c = 0; c < NBUF; c++) {
                uint32_t mb  = sb + SM_MB + c * 8;
                uint32_t dst = sb + SM_AB + c * ABUF;
                MBARRIER_EXPECT_TX(mb, ABUF);
                bulk_g2s(dst,          hsrc + (size_t)c * CKROWS * 72,                    APLANE, mb);
                bulk_g2s(dst + APLANE, hsrc + (size_t)HID * 72 + (size_t)c * CKROWS * 72, APLANE, mb);
            }
        }

        const float* xp = g_xproj + (size_t)t * BATCH * G4 + (size_t)col * 4;
        float4 xg0 = *(const float4*)(xp + (size_t)b0 * G4);
        float4 xg1 = *(const float4*)(xp + (size_t)b1 * G4);

        float am[2][4], ac[2][4];
#pragma unroll
        for (int p = 0; p < 2; p++)
#pragma unroll
            for (int c = 0; c < 4; c++) { am[p][c] = 0.f; ac[p][c] = 0.f; }

        for (int c4 = 0; c4 < 4; c4++) {
#pragma unroll
            for (int buf = 0; buf < NBUF; buf++) {
                const int c = c4 * 4 + buf;
                MBARRIER_WAIT_PARITY(sb + SM_MB + buf * 8, ph[buf]);
                ph[buf] ^= 1;
                const uint32_t aHi = sb + SM_AB + buf * ABUF;
#pragma unroll
                for (int s = 0; s < 4; s++) {
                    uint32_t ao = aHi + (s * 16 + aK) * AROWB + aMb;
                    uint32_t ah0, ah1, ah2, ah3, al0, al1, al2, al3;
                    LDSM_X4T(ah0, ah1, ah2, ah3, ao);
                    LDSM_X4T(al0, al1, al2, al3, ao + APLANE);
                    uint32_t bo = bRowOff + (uint32_t)((c * CKROWS + s * 16 + bK8) << 1);
                    uint32_t bh0, bh1, bh2, bh3, bl0, bl1, bl2, bl3;
                    LDSM_X4(bh0, bh1, bh2, bh3, sb + SM_W + bo);
                    LDSM_X4(bl0, bl1, bl2, bl3, sb + SM_W + WPLANE + bo);
                    mma_bf16(am[0][0], am[0][1], am[0][2], am[0][3], ah0, ah1, ah2, ah3, bh0, bh1);
                    mma_bf16(am[1][0], am[1][1], am[1][2], am[1][3], ah0, ah1, ah2, ah3, bh2, bh3);
                    mma_bf16(ac[0][0], ac[0][1], ac[0][2], ac[0][3], ah0, ah1, ah2, ah3, bl0, bl1);
                    mma_bf16(ac[0][0], ac[0][1], ac[0][2], ac[0][3], al0, al1, al2, al3, bh0, bh1);
                    mma_bf16(ac[1][0], ac[1][1], ac[1][2], ac[1][3], ah0, ah1, ah2, ah3, bl2, bl3);
                    mma_bf16(ac[1][0], ac[1][1], ac[1][2], ac[1][3], al0, al1, al2, al3, bh2, bh3);
                }
                __syncthreads();
                if (tid == 0 && c + NBUF < CHUNKS) {
                    const int cn = c + NBUF;
                    uint32_t mb  = sb + SM_MB + buf * 8;
                    uint32_t dst = aHi;
                    MBARRIER_EXPECT_TX(mb, ABUF);
                    bulk_g2s(dst,          hsrc + (size_t)cn * CKROWS * 72,                    APLANE, mb);
                    bulk_g2s(dst + APLANE, hsrc + (size_t)HID * 72 + (size_t)cn * CKROWS * 72, APLANE, mb);
                }
            }
        }

        // in-register cell update (gates i,f in am/ac[0], g,o in am/ac[1])
        float ig0 = sigmoidf_(am[0][0] + ac[0][0] + xg0.x);
        float fg0 = sigmoidf_(am[0][1] + ac[0][1] + xg0.y);
        float gg0 = tanhf    (am[1][0] + ac[1][0] + xg0.z);
        float og0 = sigmoidf_(am[1][1] + ac[1][1] + xg0.w);
        c0r = fg0 * c0r + ig0 * gg0;
        float hv0 = og0 * tanhf(c0r);

        float ig1 = sigmoidf_(am[0][2] + ac[0][2] + xg1.x);
        float fg1 = sigmoidf_(am[0][3] + ac[0][3] + xg1.y);
        float gg1 = tanhf    (am[1][2] + ac[1][2] + xg1.z);
        float og1 = sigmoidf_(am[1][3] + ac[1][3] + xg1.w);
        c1r = fg1 * c1r + ig1 * gg1;
        float hv1 = og1 * tanhf(c1r);

        // stage hT slice in smem (rows 0-7 hi, 8-15 lo; pitch 136B)
        const int wbuf = (t + 1) & 1;
        {
            char* st = smem + SM_ST;
            __nv_bfloat16 h0h = __float2bfloat16_rn(hv0);
            __nv_bfloat16 h1h = __float2bfloat16_rn(hv1);
            *(__nv_bfloat16*)(st + jloc * 136 + b0 * 2) = h0h;
            *(__nv_bfloat16*)(st + jloc * 136 + b1 * 2) = h1h;
            *(__nv_bfloat16*)(st + (8 + jloc) * 136 + b0 * 2) =
                __float2bfloat16_rn(hv0 - __bfloat162float(h0h));
            *(__nv_bfloat16*)(st + (8 + jloc) * 136 + b1 * 2) =
                __float2bfloat16_rn(hv1 - __bfloat162float(h1h));
        }

        out[((size_t)t * BATCH + b0) * HID + col] = hv0;
        out[((size_t)t * BATCH + b1) * HID + col] = hv1;

        __syncthreads();
        // coalesced hT writeback: 16 rows x 128B
        {
            int row = tid >> 4, sub = tid & 15;
            uint2 v = *(uint2*)(smem + SM_ST + row * 136 + sub * 8);
            int plane = row >> 3, jl = row & 7;
            *(uint2*)&g_hT[wbuf][plane][hb + jl][sub * 4] = v;
        }

        if (t == T_STEPS - 1) {
            const long long need = (long long)T_STEPS * BATCH * HID + 2LL * BATCH * HID;
            if ((long long)out_size >= need) {
                size_t base = (size_t)T_STEPS * BATCH * HID;
                out[base + (size_t)b0 * HID + col] = hv0;
                out[base + (size_t)b1 * HID + col] = hv1;
                out[base + (size_t)BATCH * HID + (size_t)b0 * HID + col] = c0r;
                out[base + (size_t)BATCH * HID + (size_t)b1 * HID + col] = c1r;
            }
        } else {
            __threadfence();
            __syncthreads();
            if (tid == 0) ((volatile int*)g_flags)[blk] = t + 1;
            if (tid < NBLK) {
                while (((volatile int*)g_flags)[tid] < t + 1) { __nanosleep(32); }
            }
            __threadfence();
            __syncthreads();
        }
    }
}

// ================= launch =================
extern "C" void kernel_launch(void* const* d_in, const int* in_sizes, int n_in,
                              void* d_out, int out_size) {
    const float* x    = (const float*)d_in[0];
    const float* h0   = (const float*)d_in[1];
    const float* c0   = (const float*)d_in[2];
    const float* w_ih = (const float*)d_in[3];
    const float* w_hh = (const float*)d_in[4];
    const float* b_ih = (const float*)d_in[5];
    const float* b_hh = (const float*)d_in[6];
    float* out = (float*)d_out;

    cudaFuncSetAttribute(xproj_mma,
                         cudaFuncAttributeMaxDynamicSharedMemorySize, XP_SMEM);
    cudaFuncSetAttribute(lstm_rec_tma,
                         cudaFuncAttributeMaxDynamicSharedMemorySize, R_SMEM);

    split_inputs<<<2048, 256>>>(x, w_ih, h0);
    dim3 gx(G4 / 128, (T_STEPS * BATCH) / 128);   // 32 x 512
    xproj_mma<<<gx, 256, XP_SMEM>>>(b_ih, b_hh);
    lstm_rec_tma<<<NBLK, 256, R_SMEM>>>(c0, w_hh, out, out_size);
}

// round 7
// speedup vs baseline: 1.2499x; 1.2499x over previous
#include <cuda_runtime.h>
#include <cuda_bf16.h>
#include <math.h>
#include <stdint.h>

#define T_STEPS 1024
#define BATCH   64
#define INDIM   512
#define HID     1024
#define G4      4096

#define NBLK 128

// W-resident smem geometry (proven in R6)
#define WROWB   2064                 // 1032 bf16 per W row (1024 + 8 pad)
#define WPLANE  (32 * WROWB)         // 66048
#define SM_W    0
#define SM_STAGE (2 * WPLANE)        // 132096
#define R_SMEM  (SM_STAGE + 2048)    // 134144

// ---------------- device scratch (static) ----------------
__device__ float          g_xproj[(size_t)T_STEPS * BATCH * G4];   // [t][b][j*4+gate]
__device__ __nv_bfloat16  g_xhi[(size_t)T_STEPS * BATCH * INDIM];
__device__ __nv_bfloat16  g_xlo[(size_t)T_STEPS * BATCH * INDIM];
__device__ __nv_bfloat16  g_wihhi[(size_t)G4 * INDIM];
__device__ __nv_bfloat16  g_wihlo[(size_t)G4 * INDIM];
// h packed in m16n8k16 A-fragment order: [buf][plane hi/lo][rb=b>>4][kg=k>>4][lane] = uint4 {a0,a1,a2,a3}
__device__ uint4          g_hpk[2][2][4][64][32];
__device__ int            g_flags[NBLK];

// ---------------- helpers ----------------
__device__ __forceinline__ uint32_t smem_u32(const void* p) {
    uint32_t a;
    asm("{ .reg .u64 t; cvta.to.shared.u64 t, %1; cvt.u32.u64 %0, t; }" : "=r"(a) : "l"(p));
    return a;
}

#define LDSM_X4(r0,r1,r2,r3,addr) \
    asm volatile("ldmatrix.sync.aligned.m8n8.x4.shared.b16 {%0,%1,%2,%3}, [%4];" \
                 : "=r"(r0), "=r"(r1), "=r"(r2), "=r"(r3) : "r"(addr))

__device__ __forceinline__ void mma_bf16(float& d0, float& d1, float& d2, float& d3,
                                         uint32_t a0, uint32_t a1, uint32_t a2, uint32_t a3,
                                         uint32_t b0, uint32_t b1) {
    asm volatile(
        "mma.sync.aligned.m16n8k16.row.col.f32.bf16.bf16.f32 "
        "{%0,%1,%2,%3}, {%4,%5,%6,%7}, {%8,%9}, {%0,%1,%2,%3};"
        : "+f"(d0), "+f"(d1), "+f"(d2), "+f"(d3)
        : "r"(a0), "r"(a1), "r"(a2), "r"(a3), "r"(b0), "r"(b1));
}

__device__ __forceinline__ void cp16(uint32_t dst, const void* src) {
    asm volatile("cp.async.cg.shared.global [%0], [%1], 16;" :: "r"(dst), "l"(src) : "memory");
}
#define CP_COMMIT() asm volatile("cp.async.commit_group;" ::: "memory")
#define CP_WAIT(n)  asm volatile("cp.async.wait_group %0;" :: "n"(n) : "memory")

__device__ __forceinline__ void split4(float4 v, uint2& hip, uint2& lop) {
    __nv_bfloat16 hx = __float2bfloat16_rn(v.x);
    __nv_bfloat16 hy = __float2bfloat16_rn(v.y);
    __nv_bfloat16 hz = __float2bfloat16_rn(v.z);
    __nv_bfloat16 hw = __float2bfloat16_rn(v.w);
    __nv_bfloat162 p0 = __halves2bfloat162(hx, hy);
    __nv_bfloat162 p1 = __halves2bfloat162(hz, hw);
    hip.x = *reinterpret_cast<unsigned*>(&p0);
    hip.y = *reinterpret_cast<unsigned*>(&p1);
    __nv_bfloat162 q0 = __floats2bfloat162_rn(v.x - __bfloat162float(hx),
                                              v.y - __bfloat162float(hy));
    __nv_bfloat162 q1 = __floats2bfloat162_rn(v.z - __bfloat162float(hz),
                                              v.w - __bfloat162float(hw));
    lop.x = *reinterpret_cast<unsigned*>(&q0);
    lop.y = *reinterpret_cast<unsigned*>(&q1);
}

__device__ __forceinline__ float sigmoidf_(float x) { return 1.0f / (1.0f + __expf(-x)); }

// ================= split pass =================
__global__ __launch_bounds__(256) void split_inputs(
    const float* __restrict__ x,
    const float* __restrict__ wih,
    const float* __restrict__ h0)
{
    if (blockIdx.x == 0 && threadIdx.x < NBLK) g_flags[threadIdx.x] = 0;

    const size_t NX  = (size_t)T_STEPS * BATCH * INDIM / 4;
    const size_t NW  = (size_t)G4 * INDIM / 4;
    const size_t NH0 = (size_t)BATCH * HID / 4;
    const size_t total = NX + NW + NH0;
    for (size_t i = (size_t)blockIdx.x * blockDim.x + threadIdx.x;
         i < total; i += (size_t)gridDim.x * blockDim.x) {
        if (i < NX) {
            float4 v = ((const float4*)x)[i];
            uint2 h, l; split4(v, h, l);
            ((uint2*)g_xhi)[i] = h;
            ((uint2*)g_xlo)[i] = l;
        } else if (i < NX + NW) {
            size_t k = i - NX;
            float4 v = ((const float4*)wih)[k];
            uint2 h, l; split4(v, h, l);
            ((uint2*)g_wihhi)[k] = h;
            ((uint2*)g_wihlo)[k] = l;
        } else {
            // h0 -> packed fragment layout, buffer 0
            size_t e4 = i - NX - NW;
            size_t e  = e4 * 4;
            int b = (int)(e >> 10);
            int kbase = (int)(e & 1023);
            float4 v = ((const float4*)h0)[e4];
            float vv[4] = {v.x, v.y, v.z, v.w};
            int r  = b & 15;
            int rb = b >> 4;
#pragma unroll
            for (int q = 0; q < 4; q++) {
                int k  = kbase + q;
                int kg = k >> 4, kk = k & 15;
                int lanep = ((r & 7) << 2) + ((kk & 7) >> 1);
                int reg   = ((kk >= 8) ? 2 : 0) + ((r >= 8) ? 1 : 0);
                int byte_ = kk & 1;
                __nv_bfloat16 hi = __float2bfloat16_rn(vv[q]);
                __nv_bfloat16 lo = __float2bfloat16_rn(vv[q] - __bfloat162float(hi));
                ((__nv_bfloat16*)&g_hpk[0][0][rb][kg][lanep])[reg * 2 + byte_] = hi;
                ((__nv_bfloat16*)&g_hpk[0][1][rb][kg][lanep])[reg * 2 + byte_] = lo;
            }
        }
    }
}

// ================= x_proj GEMM (cp.async-pipelined bf16-split HMMA) =================
#define XP_ROWB 144
#define XP_TILE (128 * XP_ROWB)
#define XP_BUF  (4 * XP_TILE)
#define XP_SMEM (2 * XP_BUF)

__global__ __launch_bounds__(256) void xproj_mma(
    const float* __restrict__ bih,
    const float* __restrict__ bhh)
{
    extern __shared__ char smem[];
    const uint32_t sb = smem_u32(smem);
    const int tid  = threadIdx.x;
    const int lane = tid & 31;
    const int w    = tid >> 5;
    const int wm   = w & 1;
    const int wn   = w >> 1;
    const int jb   = blockIdx.x * 32;
    const size_t mb = (size_t)blockIdx.y * 128;

    float acc[4][4][4];
#pragma unroll
    for (int a = 0; a < 4; a++)
#pragma unroll
        for (int b = 0; b < 4; b++)
#pragma unroll
            for (int c = 0; c < 4; c++) acc[a][b][c] = 0.f;

    const int a_row = wm * 64 + (lane & 7) + ((lane >> 3) & 1) * 8;
    const int a_k8  = (lane >> 4) * 8;
    const int b_row = wn * 32 + (lane & 7) + (lane >> 4) * 8;
    const int b_k8  = ((lane >> 3) & 1) * 8;

    int st_row[4], st_c[4], st_wrow[4];
#pragma unroll
    for (int q = 0; q < 4; q++) {
        int s = tid * 4 + q;
        st_row[q]  = s >> 3;
        st_c[q]    = s & 7;
        st_wrow[q] = (st_row[q] & 3) * HID + jb + (st_row[q] >> 2);
    }

    auto stage = [&](int kb, int buf) {
        uint32_t base = sb + buf * XP_BUF;
#pragma unroll
        for (int q = 0; q < 4; q++) {
            size_t gk = (size_t)kb * 64 + st_c[q] * 8;
            uint32_t off = st_row[q] * XP_ROWB + st_c[q] * 16;
            cp16(base + 0 * XP_TILE + off, &g_xhi[(mb + st_row[q]) * INDIM + gk]);
            cp16(base + 1 * XP_TILE + off, &g_xlo[(mb + st_row[q]) * INDIM + gk]);
            cp16(base + 2 * XP_TILE + off, &g_wihhi[(size_t)st_wrow[q] * INDIM + gk]);
            cp16(base + 3 * XP_TILE + off, &g_wihlo[(size_t)st_wrow[q] * INDIM + gk]);
        }
        CP_COMMIT();
    };

    stage(0, 0);

    for (int kb = 0; kb < 8; kb++) {
        const int buf = kb & 1;
        if (kb < 7) stage(kb + 1, buf ^ 1);
        if (kb < 7) { CP_WAIT(1); } else { CP_WAIT(0); }
        __syncthreads();

        const uint32_t aHi = sb + buf * XP_BUF;
        const uint32_t aLo = aHi + XP_TILE;
        const uint32_t bHi = aHi + 2 * XP_TILE;
        const uint32_t bLo = aHi + 3 * XP_TILE;

#pragma unroll
        for (int s = 0; s < 4; s++) {
            uint32_t bh[8], bl[8];
#pragma unroll
            for (int p = 0; p < 2; p++) {
                uint32_t off = (b_row + p * 16) * XP_ROWB + (s * 16 + b_k8) * 2;
                LDSM_X4(bh[p*4+0], bh[p*4+1], bh[p*4+2], bh[p*4+3], bHi + off);
                LDSM_X4(bl[p*4+0], bl[p*4+1], bl[p*4+2], bl[p*4+3], bLo + off);
            }
#pragma unroll
            for (int mt = 0; mt < 4; mt++) {
                uint32_t off = (a_row + mt * 16) * XP_ROWB + (s * 16 + a_k8) * 2;
                uint32_t ah0, ah1, ah2, ah3, al0, al1, al2, al3;
                LDSM_X4(ah0, ah1, ah2, ah3, aHi + off);
                LDSM_X4(al0, al1, al2, al3, aLo + off);
#pragma unroll
                for (int nt = 0; nt < 4; nt++) {
                    float* d = acc[mt][nt];
                    mma_bf16(d[0], d[1], d[2], d[3], ah0, ah1, ah2, ah3, bh[nt*2], bh[nt*2+1]);
                    mma_bf16(d[0], d[1], d[2], d[3], ah0, ah1, ah2, ah3, bl[nt*2], bl[nt*2+1]);
                    mma_bf16(d[0], d[1], d[2], d[3], al0, al1, al2, al3, bh[nt*2], bh[nt*2+1]);
                }
            }
        }
        __syncthreads();
    }

    const int colq = (lane & 3) * 2;
#pragma unroll
    for (int nt = 0; nt < 4; nt++) {
        int nloc = wn * 32 + nt * 8 + colq;
        int g0 = nloc & 3,        j0 = jb + (nloc >> 2);
        int g1 = (nloc + 1) & 3,  j1 = jb + ((nloc + 1) >> 2);
        float bb0 = bih[g0 * HID + j0] + bhh[g0 * HID + j0];
        float bb1 = bih[g1 * HID + j1] + bhh[g1 * HID + j1];
#pragma unroll
        for (int mt = 0; mt < 4; mt++) {
            size_t r0 = mb + wm * 64 + mt * 16 + (lane >> 2);
            float2 v0 = make_float2(acc[mt][nt][0] + bb0, acc[mt][nt][1] + bb1);
            float2 v1 = make_float2(acc[mt][nt][2] + bb0, acc[mt][nt][3] + bb1);
            *(float2*)&g_xproj[r0 * G4 + jb * 4 + nloc]       = v0;
            *(float2*)&g_xproj[(r0 + 8) * G4 + jb * 4 + nloc] = v1;
        }
    }
}

// ================= persistent recurrent kernel (packed-fragment LDG A path) =================
__global__ __launch_bounds__(256, 1) void lstm_rec_pk(
    const float* __restrict__ c0in,
    const float* __restrict__ whh,
    float* __restrict__ out, int out_size)
{
    extern __shared__ char smem[];
    const uint32_t sb = smem_u32(smem);
    const int tid  = threadIdx.x;
    const int lane = tid & 31;
    const int w    = tid >> 5;
    const int mt   = w & 3;
    const int nh   = w >> 2;
    const int blk  = blockIdx.x;
    const int hb   = blk * 8;
    const int kgc  = blk >> 1;   // this CTA's columns live in frag-group kgc

    // one-time: W slice -> smem (gate-interleaved rows, proven R6 mapping), hi+lo
    for (int it = 0; it < 32; it++) {
        int e4 = it * 256 + tid;
        int n  = e4 >> 8;
        int kf = (e4 & 255) * 4;
        int nh_ = n >> 4, r = n & 15;
        int nt = r >> 3, q = (r & 7) >> 1, low = r & 1;
        int gate = nt * 2 + low, j = 4 * nh_ + q;
        float4 v = *(const float4*)&whh[(size_t)(gate * HID + hb + j) * HID + kf];
        uint2 hp, lp; split4(v, hp, lp);
        *(uint2*)(smem + SM_W + n * WROWB + kf * 2) = hp;
        *(uint2*)(smem + SM_W + WPLANE + n * WROWB + kf * 2) = lp;
    }
    __syncthreads();

    const uint32_t bRowOff = (uint32_t)(nh * 16 + (lane & 7) + ((lane >> 4) << 3)) * WROWB;
    const uint32_t bK8 = ((lane >> 3) & 1) * 8;

    const int b0  = mt * 16 + (lane >> 2);
    const int b1  = b0 + 8;
    const int jloc = 4 * nh + (lane & 3);
    const int col = hb + jloc;

    // stage smem offsets for hT writeback
    const int lane_t = ((lane >> 2) << 2) + (jloc >> 1);
    const uint32_t offB0 = (uint32_t)(mt * 32 + lane_t) * 8 + (jloc & 1) * 2;  // plane0, reg0
    // b1 -> +4 ; plane1 -> +1024

    float c0r = c0in[b0 * HID + col];
    float c1r = c0in[b1 * HID + col];

    for (int t = 0; t < T_STEPS; t++) {
        const int rbuf = t & 1;
        const uint4* __restrict__ Ah = &g_hpk[rbuf][0][mt][0][lane];
        const uint4* __restrict__ Al = &g_hpk[rbuf][1][mt][0][lane];

        const float* xp = g_xproj + (size_t)t * BATCH * G4 + (size_t)col * 4;
        float4 xg0 = *(const float4*)(xp + (size_t)b0 * G4);
        float4 xg1 = *(const float4*)(xp + (size_t)b1 * G4);

        float am0[4], am1[4], a10[4], a11[4], a20[4], a21[4];
#pragma unroll
        for (int c = 0; c < 4; c++) {
            am0[c] = 0.f; am1[c] = 0.f;
            a10[c] = 0.f; a11[c] = 0.f;
            a20[c] = 0.f; a21[c] = 0.f;
        }

        uint4 pah[4], pal[4];
#pragma unroll
        for (int i = 0; i < 4; i++) { pah[i] = Ah[i * 32]; pal[i] = Al[i * 32]; }

        for (int kg4 = 0; kg4 < 16; kg4++) {
#pragma unroll
            for (int u = 0; u < 4; u++) {
                const int kg = kg4 * 4 + u;
                uint32_t ah0 = pah[u].x, ah1 = pah[u].y, ah2 = pah[u].z, ah3 = pah[u].w;
                uint32_t al0 = pal[u].x, al1 = pal[u].y, al2 = pal[u].z, al3 = pal[u].w;
                if (kg4 < 15) { pah[u] = Ah[(kg + 4) * 32]; pal[u] = Al[(kg + 4) * 32]; }
                uint32_t bo = bRowOff + (uint32_t)((kg * 16 + bK8) << 1);
                uint32_t bh0, bh1, bh2, bh3, bl0, bl1, bl2, bl3;
                LDSM_X4(bh0, bh1, bh2, bh3, sb + SM_W + bo);
                LDSM_X4(bl0, bl1, bl2, bl3, sb + SM_W + WPLANE + bo);
                mma_bf16(am0[0], am0[1], am0[2], am0[3], ah0, ah1, ah2, ah3, bh0, bh1);
                mma_bf16(am1[0], am1[1], am1[2], am1[3], ah0, ah1, ah2, ah3, bh2, bh3);
                mma_bf16(a10[0], a10[1], a10[2], a10[3], ah0, ah1, ah2, ah3, bl0, bl1);
                mma_bf16(a11[0], a11[1], a11[2], a11[3], ah0, ah1, ah2, ah3, bl2, bl3);
                mma_bf16(a20[0], a20[1], a20[2], a20[3], al0, al1, al2, al3, bh0, bh1);
                mma_bf16(a21[0], a21[1], a21[2], a21[3], al0, al1, al2, al3, bh2, bh3);
            }
        }

        // gate sums (tile0 = gates 0,1 ; tile1 = gates 2,3 per R6's W-row permutation)
        float g00 = am0[0] + a10[0] + a20[0];
        float g01 = am0[1] + a10[1] + a20[1];
        float g02 = am0[2] + a10[2] + a20[2];
        float g03 = am0[3] + a10[3] + a20[3];
        float g10 = am1[0] + a11[0] + a21[0];
        float g11 = am1[1] + a11[1] + a21[1];
        float g12 = am1[2] + a11[2] + a21[2];
        float g13 = am1[3] + a11[3] + a21[3];

        float ig0 = sigmoidf_(g00 + xg0.x);
        float fg0 = sigmoidf_(g01 + xg0.y);
        float gg0 = tanhf    (g10 + xg0.z);
        float og0 = sigmoidf_(g11 + xg0.w);
        c0r = fg0 * c0r + ig0 * gg0;
        float hv0 = og0 * tanhf(c0r);

        float ig1 = sigmoidf_(g02 + xg1.x);
        float fg1 = sigmoidf_(g03 + xg1.y);
        float gg1 = tanhf    (g12 + xg1.z);
        float og1 = sigmoidf_(g13 + xg1.w);
        c1r = fg1 * c1r + ig1 * gg1;
        float hv1 = og1 * tanhf(c1r);

        // stage packed-h slice in smem
        {
            char* st = smem + SM_STAGE;
            __nv_bfloat16 h0h = __float2bfloat16_rn(hv0);
            __nv_bfloat16 h1h = __float2bfloat16_rn(hv1);
            *(__nv_bfloat16*)(st + offB0)        = h0h;       // plane0, b0 (reg0)
            *(__nv_bfloat16*)(st + offB0 + 4)    = h1h;       // plane0, b1 (reg1)
            *(__nv_bfloat16*)(st + offB0 + 1024) =
                __float2bfloat16_rn(hv0 - __bfloat162float(h0h));
            *(__nv_bfloat16*)(st + offB0 + 1028) =
                __float2bfloat16_rn(hv1 - __bfloat162float(h1h));
        }

        out[((size_t)t * BATCH + b0) * HID + col] = hv0;
        out[((size_t)t * BATCH + b1) * HID + col] = hv1;

        __syncthreads();
        // coalesced packed writeback: 256 threads, one STG.64 each
        {
            const int wbuf = (t + 1) & 1;
            int plane = tid >> 7, rb = (tid >> 5) & 3, lt = tid & 31;
            uint2 v = *(uint2*)(smem + SM_STAGE + (uint32_t)((plane * 4 + rb) * 32 + lt) * 8);
            uint2* dst = (uint2*)&g_hpk[wbuf][plane][rb][kgc][lt];
            dst[blk & 1] = v;
        }

        if (t == T_STEPS - 1) {
            const long long need = (long long)T_STEPS * BATCH * HID + 2LL * BATCH * HID;
            if ((long long)out_size >= need) {
                size_t base = (size_t)T_STEPS * BATCH * HID;
                out[base + (size_t)b0 * HID + col] = hv0;
                out[base + (size_t)b1 * HID + col] = hv1;
                out[base + (size_t)BATCH * HID + (size_t)b0 * HID + col] = c0r;
                out[base + (size_t)BATCH * HID + (size_t)b1 * HID + col] = c1r;
            }
        } else {
            __threadfence();           // release packed-h stores (also CCTL.IVALL)
            __syncthreads();
            if (tid == 0) ((volatile int*)g_flags)[blk] = t + 1;
            if (tid < NBLK) {
                while (((volatile int*)g_flags)[tid] < t + 1) { __nanosleep(32); }
            }
            __threadfence();           // acquire + invalidate L1 before new h reads
            __syncthreads();
        }
    }
}

// ================= launch =================
extern "C" void kernel_launch(void* const* d_in, const int* in_sizes, int n_in,
                              void* d_out, int out_size) {
    const float* x    = (const float*)d_in[0];
    const float* h0   = (const float*)d_in[1];
    const float* c0   = (const float*)d_in[2];
    const float* w_ih = (const float*)d_in[3];
    const float* w_hh = (const float*)d_in[4];
    const float* b_ih = (const float*)d_in[5];
    const float* b_hh = (const float*)d_in[6];
    float* out = (float*)d_out;

    cudaFuncSetAttribute(xproj_mma,
                         cudaFuncAttributeMaxDynamicSharedMemorySize, XP_SMEM);
    cudaFuncSetAttribute(lstm_rec_pk,
                         cudaFuncAttributeMaxDynamicSharedMemorySize, R_SMEM);

    split_inputs<<<2048, 256>>>(x, w_ih, h0);
    dim3 gx(G4 / 128, (T_STEPS * BATCH) / 128);   // 32 x 512
    xproj_mma<<<gx, 256, XP_SMEM>>>(b_ih, b_hh);
    lstm_rec_pk<<<NBLK, 256, R_SMEM>>>(c0, w_hh, out, out_size);
}

// round 8
// speedup vs baseline: 1.3663x; 1.0931x over previous
#include <cuda_runtime.h>
#include <cuda_bf16.h>
#include <math.h>
#include <stdint.h>

#define T_STEPS 1024
#define BATCH   64
#define INDIM   512
#define HID     1024
#define G4      4096

#define NBLK 128

// W-resident smem geometry (proven in R6/R7)
#define WROWB   2064                 // 1032 bf16 per W row (1024 + 8 pad)
#define WPLANE  (32 * WROWB)         // 66048
#define SM_W    0
#define SM_STAGE (2 * WPLANE)        // 132096
#define R_SMEM  (SM_STAGE + 2048)    // 134144

// ---------------- device scratch (static) ----------------
__device__ float          g_xproj[(size_t)T_STEPS * BATCH * G4];   // [t][b][j*4+gate]
__device__ __nv_bfloat16  g_xhi[(size_t)T_STEPS * BATCH * INDIM];
__device__ __nv_bfloat16  g_xlo[(size_t)T_STEPS * BATCH * INDIM];
__device__ __nv_bfloat16  g_wihhi[(size_t)G4 * INDIM];
__device__ __nv_bfloat16  g_wihlo[(size_t)G4 * INDIM];
// h packed in m16n8k16 A-fragment order: [buf][plane hi/lo][rb=b>>4][kg=k>>4][lane] = uint4 {a0,a1,a2,a3}
__device__ uint4          g_hpk[2][2][4][64][32];
__device__ int            g_flags[NBLK];

// ---------------- helpers ----------------
__device__ __forceinline__ uint32_t smem_u32(const void* p) {
    uint32_t a;
    asm("{ .reg .u64 t; cvta.to.shared.u64 t, %1; cvt.u32.u64 %0, t; }" : "=r"(a) : "l"(p));
    return a;
}

#define LDSM_X4(r0,r1,r2,r3,addr) \
    asm volatile("ldmatrix.sync.aligned.m8n8.x4.shared.b16 {%0,%1,%2,%3}, [%4];" \
                 : "=r"(r0), "=r"(r1), "=r"(r2), "=r"(r3) : "r"(addr))

__device__ __forceinline__ void mma_bf16(float& d0, float& d1, float& d2, float& d3,
                                         uint32_t a0, uint32_t a1, uint32_t a2, uint32_t a3,
                                         uint32_t b0, uint32_t b1) {
    asm volatile(
        "mma.sync.aligned.m16n8k16.row.col.f32.bf16.bf16.f32 "
        "{%0,%1,%2,%3}, {%4,%5,%6,%7}, {%8,%9}, {%0,%1,%2,%3};"
        : "+f"(d0), "+f"(d1), "+f"(d2), "+f"(d3)
        : "r"(a0), "r"(a1), "r"(a2), "r"(a3), "r"(b0), "r"(b1));
}

__device__ __forceinline__ void cp16(uint32_t dst, const void* src) {
    asm volatile("cp.async.cg.shared.global [%0], [%1], 16;" :: "r"(dst), "l"(src) : "memory");
}
#define CP_COMMIT() asm volatile("cp.async.commit_group;" ::: "memory")
#define CP_WAIT(n)  asm volatile("cp.async.wait_group %0;" :: "n"(n) : "memory")

__device__ __forceinline__ void split4(float4 v, uint2& hip, uint2& lop) {
    __nv_bfloat16 hx = __float2bfloat16_rn(v.x);
    __nv_bfloat16 hy = __float2bfloat16_rn(v.y);
    __nv_bfloat16 hz = __float2bfloat16_rn(v.z);
    __nv_bfloat16 hw = __float2bfloat16_rn(v.w);
    __nv_bfloat162 p0 = __halves2bfloat162(hx, hy);
    __nv_bfloat162 p1 = __halves2bfloat162(hz, hw);
    hip.x = *reinterpret_cast<unsigned*>(&p0);
    hip.y = *reinterpret_cast<unsigned*>(&p1);
    __nv_bfloat162 q0 = __floats2bfloat162_rn(v.x - __bfloat162float(hx),
                                              v.y - __bfloat162float(hy));
    __nv_bfloat162 q1 = __floats2bfloat162_rn(v.z - __bfloat162float(hz),
                                              v.w - __bfloat162float(hw));
    lop.x = *reinterpret_cast<unsigned*>(&q0);
    lop.y = *reinterpret_cast<unsigned*>(&q1);
}

__device__ __forceinline__ float sigmoidf_(float x) { return 1.0f / (1.0f + __expf(-x)); }

// ================= split pass =================
__global__ __launch_bounds__(256) void split_inputs(
    const float* __restrict__ x,
    const float* __restrict__ wih,
    const float* __restrict__ h0)
{
    if (blockIdx.x == 0 && threadIdx.x < NBLK) g_flags[threadIdx.x] = 0;

    const size_t NX  = (size_t)T_STEPS * BATCH * INDIM / 4;
    const size_t NW  = (size_t)G4 * INDIM / 4;
    const size_t NH0 = (size_t)BATCH * HID / 4;
    const size_t total = NX + NW + NH0;
    for (size_t i = (size_t)blockIdx.x * blockDim.x + threadIdx.x;
         i < total; i += (size_t)gridDim.x * blockDim.x) {
        if (i < NX) {
            float4 v = ((const float4*)x)[i];
            uint2 h, l; split4(v, h, l);
            ((uint2*)g_xhi)[i] = h;
            ((uint2*)g_xlo)[i] = l;
        } else if (i < NX + NW) {
            size_t k = i - NX;
            float4 v = ((const float4*)wih)[k];
            uint2 h, l; split4(v, h, l);
            ((uint2*)g_wihhi)[k] = h;
            ((uint2*)g_wihlo)[k] = l;
        } else {
            // h0 -> packed fragment layout, buffer 0
            size_t e4 = i - NX - NW;
            size_t e  = e4 * 4;
            int b = (int)(e >> 10);
            int kbase = (int)(e & 1023);
            float4 v = ((const float4*)h0)[e4];
            float vv[4] = {v.x, v.y, v.z, v.w};
            int r  = b & 15;
            int rb = b >> 4;
#pragma unroll
            for (int q = 0; q < 4; q++) {
                int k  = kbase + q;
                int kg = k >> 4, kk = k & 15;
                int lanep = ((r & 7) << 2) + ((kk & 7) >> 1);
                int reg   = ((kk >= 8) ? 2 : 0) + ((r >= 8) ? 1 : 0);
                int byte_ = kk & 1;
                __nv_bfloat16 hi = __float2bfloat16_rn(vv[q]);
                __nv_bfloat16 lo = __float2bfloat16_rn(vv[q] - __bfloat162float(hi));
                ((__nv_bfloat16*)&g_hpk[0][0][rb][kg][lanep])[reg * 2 + byte_] = hi;
                ((__nv_bfloat16*)&g_hpk[0][1][rb][kg][lanep])[reg * 2 + byte_] = lo;
            }
        }
    }
}

// ================= x_proj GEMM (cp.async-pipelined bf16-split HMMA) =================
#define XP_ROWB 144
#define XP_TILE (128 * XP_ROWB)
#define XP_BUF  (4 * XP_TILE)
#define XP_SMEM (2 * XP_BUF)

__global__ __launch_bounds__(256) void xproj_mma(
    const float* __restrict__ bih,
    const float* __restrict__ bhh)
{
    extern __shared__ char smem[];
    const uint32_t sb = smem_u32(smem);
    const int tid  = threadIdx.x;
    const int lane = tid & 31;
    const int w    = tid >> 5;
    const int wm   = w & 1;
    const int wn   = w >> 1;
    const int jb   = blockIdx.x * 32;
    const size_t mb = (size_t)blockIdx.y * 128;

    float acc[4][4][4];
#pragma unroll
    for (int a = 0; a < 4; a++)
#pragma unroll
        for (int b = 0; b < 4; b++)
#pragma unroll
            for (int c = 0; c < 4; c++) acc[a][b][c] = 0.f;

    const int a_row = wm * 64 + (lane & 7) + ((lane >> 3) & 1) * 8;
    const int a_k8  = (lane >> 4) * 8;
    const int b_row = wn * 32 + (lane & 7) + (lane >> 4) * 8;
    const int b_k8  = ((lane >> 3) & 1) * 8;

    int st_row[4], st_c[4], st_wrow[4];
#pragma unroll
    for (int q = 0; q < 4; q++) {
        int s = tid * 4 + q;
        st_row[q]  = s >> 3;
        st_c[q]    = s & 7;
        st_wrow[q] = (st_row[q] & 3) * HID + jb + (st_row[q] >> 2);
    }

    auto stage = [&](int kb, int buf) {
        uint32_t base = sb + buf * XP_BUF;
#pragma unroll
        for (int q = 0; q < 4; q++) {
            size_t gk = (size_t)kb * 64 + st_c[q] * 8;
            uint32_t off = st_row[q] * XP_ROWB + st_c[q] * 16;
            cp16(base + 0 * XP_TILE + off, &g_xhi[(mb + st_row[q]) * INDIM + gk]);
            cp16(base + 1 * XP_TILE + off, &g_xlo[(mb + st_row[q]) * INDIM + gk]);
            cp16(base + 2 * XP_TILE + off, &g_wihhi[(size_t)st_wrow[q] * INDIM + gk]);
            cp16(base + 3 * XP_TILE + off, &g_wihlo[(size_t)st_wrow[q] * INDIM + gk]);
        }
        CP_COMMIT();
    };

    stage(0, 0);

    for (int kb = 0; kb < 8; kb++) {
        const int buf = kb & 1;
        if (kb < 7) stage(kb + 1, buf ^ 1);
        if (kb < 7) { CP_WAIT(1); } else { CP_WAIT(0); }
        __syncthreads();

        const uint32_t aHi = sb + buf * XP_BUF;
        const uint32_t aLo = aHi + XP_TILE;
        const uint32_t bHi = aHi + 2 * XP_TILE;
        const uint32_t bLo = aHi + 3 * XP_TILE;

#pragma unroll
        for (int s = 0; s < 4; s++) {
            uint32_t bh[8], bl[8];
#pragma unroll
            for (int p = 0; p < 2; p++) {
                uint32_t off = (b_row + p * 16) * XP_ROWB + (s * 16 + b_k8) * 2;
                LDSM_X4(bh[p*4+0], bh[p*4+1], bh[p*4+2], bh[p*4+3], bHi + off);
                LDSM_X4(bl[p*4+0], bl[p*4+1], bl[p*4+2], bl[p*4+3], bLo + off);
            }
#pragma unroll
            for (int mt = 0; mt < 4; mt++) {
                uint32_t off = (a_row + mt * 16) * XP_ROWB + (s * 16 + a_k8) * 2;
                uint32_t ah0, ah1, ah2, ah3, al0, al1, al2, al3;
                LDSM_X4(ah0, ah1, ah2, ah3, aHi + off);
                LDSM_X4(al0, al1, al2, al3, aLo + off);
#pragma unroll
                for (int nt = 0; nt < 4; nt++) {
                    float* d = acc[mt][nt];
                    mma_bf16(d[0], d[1], d[2], d[3], ah0, ah1, ah2, ah3, bh[nt*2], bh[nt*2+1]);
                    mma_bf16(d[0], d[1], d[2], d[3], ah0, ah1, ah2, ah3, bl[nt*2], bl[nt*2+1]);
                    mma_bf16(d[0], d[1], d[2], d[3], al0, al1, al2, al3, bh[nt*2], bh[nt*2+1]);
                }
            }
        }
        __syncthreads();
    }

    const int colq = (lane & 3) * 2;
#pragma unroll
    for (int nt = 0; nt < 4; nt++) {
        int nloc = wn * 32 + nt * 8 + colq;
        int g0 = nloc & 3,        j0 = jb + (nloc >> 2);
        int g1 = (nloc + 1) & 3,  j1 = jb + ((nloc + 1) >> 2);
        float bb0 = bih[g0 * HID + j0] + bhh[g0 * HID + j0];
        float bb1 = bih[g1 * HID + j1] + bhh[g1 * HID + j1];
#pragma unroll
        for (int mt = 0; mt < 4; mt++) {
            size_t r0 = mb + wm * 64 + mt * 16 + (lane >> 2);
            float2 v0 = make_float2(acc[mt][nt][0] + bb0, acc[mt][nt][1] + bb1);
            float2 v1 = make_float2(acc[mt][nt][2] + bb0, acc[mt][nt][3] + bb1);
            *(float2*)&g_xproj[r0 * G4 + jb * 4 + nloc]       = v0;
            *(float2*)&g_xproj[(r0 + 8) * G4 + jb * 4 + nloc] = v1;
        }
    }
}

// ================= persistent recurrent kernel (deep-prefetch packed LDG A path) =================
__global__ __launch_bounds__(256, 1) void lstm_rec_pk(
    const float* __restrict__ c0in,
    const float* __restrict__ whh,
    float* __restrict__ out, int out_size)
{
    extern __shared__ char smem[];
    const uint32_t sb = smem_u32(smem);
    const int tid  = threadIdx.x;
    const int lane = tid & 31;
    const int w    = tid >> 5;
    const int mt   = w & 3;
    const int nh   = w >> 2;
    const int blk  = blockIdx.x;
    const int hb   = blk * 8;
    const int kgc  = blk >> 1;   // this CTA's columns live in frag-group kgc

    // one-time: W slice -> smem (gate-interleaved rows, proven mapping), hi+lo
    for (int it = 0; it < 32; it++) {
        int e4 = it * 256 + tid;
        int n  = e4 >> 8;
        int kf = (e4 & 255) * 4;
        int nh_ = n >> 4, r = n & 15;
        int nt = r >> 3, q = (r & 7) >> 1, low = r & 1;
        int gate = nt * 2 + low, j = 4 * nh_ + q;
        float4 v = *(const float4*)&whh[(size_t)(gate * HID + hb + j) * HID + kf];
        uint2 hp, lp; split4(v, hp, lp);
        *(uint2*)(smem + SM_W + n * WROWB + kf * 2) = hp;
        *(uint2*)(smem + SM_W + WPLANE + n * WROWB + kf * 2) = lp;
    }
    __syncthreads();

    const uint32_t bRowOff = (uint32_t)(nh * 16 + (lane & 7) + ((lane >> 4) << 3)) * WROWB;
    const uint32_t bK8 = ((lane >> 3) & 1) * 8;

    const int b0  = mt * 16 + (lane >> 2);
    const int b1  = b0 + 8;
    const int jloc = 4 * nh + (lane & 3);
    const int col = hb + jloc;

    // stage smem offsets for hT writeback
    const int lane_t = ((lane >> 2) << 2) + (jloc >> 1);
    const uint32_t offB0 = (uint32_t)(mt * 32 + lane_t) * 8 + (jloc & 1) * 2;  // plane0, reg0

    float c0r = c0in[b0 * HID + col];
    float c1r = c0in[b1 * HID + col];

    for (int t = 0; t < T_STEPS; t++) {
        const int rbuf = t & 1;
        const uint4* __restrict__ Ah = &g_hpk[rbuf][0][mt][0][lane];
        const uint4* __restrict__ Al = &g_hpk[rbuf][1][mt][0][lane];

        const float* xp = g_xproj + (size_t)t * BATCH * G4 + (size_t)col * 4;
        float4 xg0 = *(const float4*)(xp + (size_t)b0 * G4);
        float4 xg1 = *(const float4*)(xp + (size_t)b1 * G4);

        float am0[4], am1[4], a10[4], a11[4], a20[4], a21[4];
#pragma unroll
        for (int c = 0; c < 4; c++) {
            am0[c] = 0.f; am1[c] = 0.f;
            a10[c] = 0.f; a11[c] = 0.f;
            a20[c] = 0.f; a21[c] = 0.f;
        }

        // 16-deep A prefetch (32 outstanding LDG.128/thread)
        uint4 pah[16], pal[16];
#pragma unroll
        for (int i = 0; i < 16; i++) { pah[i] = Ah[i * 32]; pal[i] = Al[i * 32]; }

        for (int kg16 = 0; kg16 < 4; kg16++) {
#pragma unroll
            for (int u = 0; u < 16; u++) {
                const int kg = kg16 * 16 + u;
                uint32_t ah0 = pah[u].x, ah1 = pah[u].y, ah2 = pah[u].z, ah3 = pah[u].w;
                uint32_t al0 = pal[u].x, al1 = pal[u].y, al2 = pal[u].z, al3 = pal[u].w;
                if (kg16 < 3) { pah[u] = Ah[(kg + 16) * 32]; pal[u] = Al[(kg + 16) * 32]; }
                uint32_t bo = bRowOff + (uint32_t)((kg * 16 + bK8) << 1);
                uint32_t bh0, bh1, bh2, bh3, bl0, bl1, bl2, bl3;
                LDSM_X4(bh0, bh1, bh2, bh3, sb + SM_W + bo);
                LDSM_X4(bl0, bl1, bl2, bl3, sb + SM_W + WPLANE + bo);
                mma_bf16(am0[0], am0[1], am0[2], am0[3], ah0, ah1, ah2, ah3, bh0, bh1);
                mma_bf16(am1[0], am1[1], am1[2], am1[3], ah0, ah1, ah2, ah3, bh2, bh3);
                mma_bf16(a10[0], a10[1], a10[2], a10[3], ah0, ah1, ah2, ah3, bl0, bl1);
                mma_bf16(a11[0], a11[1], a11[2], a11[3], ah0, ah1, ah2, ah3, bl2, bl3);
                mma_bf16(a20[0], a20[1], a20[2], a20[3], al0, al1, al2, al3, bh0, bh1);
                mma_bf16(a21[0], a21[1], a21[2], a21[3], al0, al1, al2, al3, bh2, bh3);
            }
        }

        // gate sums (tile0 = gates 0,1 ; tile1 = gates 2,3)
        float g00 = am0[0] + a10[0] + a20[0];
        float g01 = am0[1] + a10[1] + a20[1];
        float g02 = am0[2] + a10[2] + a20[2];
        float g03 = am0[3] + a10[3] + a20[3];
        float g10 = am1[0] + a11[0] + a21[0];
        float g11 = am1[1] + a11[1] + a21[1];
        float g12 = am1[2] + a11[2] + a21[2];
        float g13 = am1[3] + a11[3] + a21[3];

        float ig0 = sigmoidf_(g00 + xg0.x);
        float fg0 = sigmoidf_(g01 + xg0.y);
        float gg0 = tanhf    (g10 + xg0.z);
        float og0 = sigmoidf_(g11 + xg0.w);
        c0r = fg0 * c0r + ig0 * gg0;
        float hv0 = og0 * tanhf(c0r);

        float ig1 = sigmoidf_(g02 + xg1.x);
        float fg1 = sigmoidf_(g03 + xg1.y);
        float gg1 = tanhf    (g12 + xg1.z);
        float og1 = sigmoidf_(g13 + xg1.w);
        c1r = fg1 * c1r + ig1 * gg1;
        float hv1 = og1 * tanhf(c1r);

        // stage packed-h slice in smem
        {
            char* st = smem + SM_STAGE;
            __nv_bfloat16 h0h = __float2bfloat16_rn(hv0);
            __nv_bfloat16 h1h = __float2bfloat16_rn(hv1);
            *(__nv_bfloat16*)(st + offB0)        = h0h;
            *(__nv_bfloat16*)(st + offB0 + 4)    = h1h;
            *(__nv_bfloat16*)(st + offB0 + 1024) =
                __float2bfloat16_rn(hv0 - __bfloat162float(h0h));
            *(__nv_bfloat16*)(st + offB0 + 1028) =
                __float2bfloat16_rn(hv1 - __bfloat162float(h1h));
        }

        __syncthreads();
        // coalesced packed writeback: 256 threads, one STG.64 each
        {
            const int wbuf = (t + 1) & 1;
            int plane = tid >> 7, rb = (tid >> 5) & 3, lt = tid & 31;
            uint2 v = *(uint2*)(smem + SM_STAGE + (uint32_t)((plane * 4 + rb) * 32 + lt) * 8);
            uint2* dst = (uint2*)&g_hpk[wbuf][plane][rb][kgc][lt];
            dst[blk & 1] = v;
        }

        if (t == T_STEPS - 1) {
            out[((size_t)t * BATCH + b0) * HID + col] = hv0;
            out[((size_t)t * BATCH + b1) * HID + col] = hv1;
            const long long need = (long long)T_STEPS * BATCH * HID + 2LL * BATCH * HID;
            if ((long long)out_size >= need) {
                size_t base = (size_t)T_STEPS * BATCH * HID;
                out[base + (size_t)b0 * HID + col] = hv0;
                out[base + (size_t)b1 * HID + col] = hv1;
                out[base + (size_t)BATCH * HID + (size_t)b0 * HID + col] = c0r;
                out[base + (size_t)BATCH * HID + (size_t)b1 * HID + col] = c1r;
            }
        } else {
            __threadfence();           // release packed-h stores
            __syncthreads();
            if (tid == 0) ((volatile int*)g_flags)[blk] = t + 1;
            // out stores off the critical path (after flag release)
            out[((size_t)t * BATCH + b0) * HID + col] = hv0;
            out[((size_t)t * BATCH + b1) * HID + col] = hv1;
            if (tid < NBLK) {
                while (((volatile int*)g_flags)[tid] < t + 1) { __nanosleep(32); }
            }
            __threadfence();           // acquire + invalidate L1 before new h reads
            __syncthreads();
        }
    }
}

// ================= launch =================
extern "C" void kernel_launch(void* const* d_in, const int* in_sizes, int n_in,
                              void* d_out, int out_size) {
    const float* x    = (const float*)d_in[0];
    const float* h0   = (const float*)d_in[1];
    const float* c0   = (const float*)d_in[2];
    const float* w_ih = (const float*)d_in[3];
    const float* w_hh = (const float*)d_in[4];
    const float* b_ih = (const float*)d_in[5];
    const float* b_hh = (const float*)d_in[6];
    float* out = (float*)d_out;

    cudaFuncSetAttribute(xproj_mma,
                         cudaFuncAttributeMaxDynamicSharedMemorySize, XP_SMEM);
    cudaFuncSetAttribute(lstm_rec_pk,
                         cudaFuncAttributeMaxDynamicSharedMemorySize, R_SMEM);

    split_inputs<<<2048, 256>>>(x, w_ih, h0);
    dim3 gx(G4 / 128, (T_STEPS * BATCH) / 128);   // 32 x 512
    xproj_mma<<<gx, 256, XP_SMEM>>>(b_ih, b_hh);
    lstm_rec_pk<<<NBLK, 256, R_SMEM>>>(c0, w_hh, out, out_size);
}

// round 9
// speedup vs baseline: 1.5516x; 1.1357x over previous
#include <cuda_runtime.h>
#include <cuda_bf16.h>
#include <math.h>
#include <stdint.h>

#define T_STEPS 1024
#define BATCH   64
#define INDIM   512
#define HID     1024
#define G4      4096

#define NBLK 128

// W-resident smem geometry (proven R6-R8)
#define WROWB   2064                 // 1032 bf16 per W row (1024 + 8 pad)
#define WPLANE  (32 * WROWB)         // 66048
#define SM_W    0
#define SM_STAGE (2 * WPLANE)        // 132096
#define SM_RED  (SM_STAGE + 2048)    // 134144 ; 8KB partial-sum exchange
#define R_SMEM  (SM_RED + 8192)      // 142336

// ---------------- device scratch (static) ----------------
__device__ float          g_xproj[(size_t)T_STEPS * BATCH * G4];   // [t][b][j*4+gate]
__device__ __nv_bfloat16  g_xhi[(size_t)T_STEPS * BATCH * INDIM];
__device__ __nv_bfloat16  g_xlo[(size_t)T_STEPS * BATCH * INDIM];
__device__ __nv_bfloat16  g_wihhi[(size_t)G4 * INDIM];
__device__ __nv_bfloat16  g_wihlo[(size_t)G4 * INDIM];
// h packed in m16n8k16 A-fragment order: [buf][plane hi/lo][rb=b>>4][kg=k>>4][lane] = uint4
__device__ uint4          g_hpk[2][2][4][64][32];
__device__ int            g_flags[NBLK];

// ---------------- helpers ----------------
__device__ __forceinline__ uint32_t smem_u32(const void* p) {
    uint32_t a;
    asm("{ .reg .u64 t; cvta.to.shared.u64 t, %1; cvt.u32.u64 %0, t; }" : "=r"(a) : "l"(p));
    return a;
}

#define LDSM_X4(r0,r1,r2,r3,addr) \
    asm volatile("ldmatrix.sync.aligned.m8n8.x4.shared.b16 {%0,%1,%2,%3}, [%4];" \
                 : "=r"(r0), "=r"(r1), "=r"(r2), "=r"(r3) : "r"(addr))

__device__ __forceinline__ void mma_bf16(float& d0, float& d1, float& d2, float& d3,
                                         uint32_t a0, uint32_t a1, uint32_t a2, uint32_t a3,
                                         uint32_t b0, uint32_t b1) {
    asm volatile(
        "mma.sync.aligned.m16n8k16.row.col.f32.bf16.bf16.f32 "
        "{%0,%1,%2,%3}, {%4,%5,%6,%7}, {%8,%9}, {%0,%1,%2,%3};"
        : "+f"(d0), "+f"(d1), "+f"(d2), "+f"(d3)
        : "r"(a0), "r"(a1), "r"(a2), "r"(a3), "r"(b0), "r"(b1));
}

__device__ __forceinline__ void cp16(uint32_t dst, const void* src) {
    asm volatile("cp.async.cg.shared.global [%0], [%1], 16;" :: "r"(dst), "l"(src) : "memory");
}
#define CP_COMMIT() asm volatile("cp.async.commit_group;" ::: "memory")
#define CP_WAIT(n)  asm volatile("cp.async.wait_group %0;" :: "n"(n) : "memory")

__device__ __forceinline__ void split4(float4 v, uint2& hip, uint2& lop) {
    __nv_bfloat16 hx = __float2bfloat16_rn(v.x);
    __nv_bfloat16 hy = __float2bfloat16_rn(v.y);
    __nv_bfloat16 hz = __float2bfloat16_rn(v.z);
    __nv_bfloat16 hw = __float2bfloat16_rn(v.w);
    __nv_bfloat162 p0 = __halves2bfloat162(hx, hy);
    __nv_bfloat162 p1 = __halves2bfloat162(hz, hw);
    hip.x = *reinterpret_cast<unsigned*>(&p0);
    hip.y = *reinterpret_cast<unsigned*>(&p1);
    __nv_bfloat162 q0 = __floats2bfloat162_rn(v.x - __bfloat162float(hx),
                                              v.y - __bfloat162float(hy));
    __nv_bfloat162 q1 = __floats2bfloat162_rn(v.z - __bfloat162float(hz),
                                              v.w - __bfloat162float(hw));
    lop.x = *reinterpret_cast<unsigned*>(&q0);
    lop.y = *reinterpret_cast<unsigned*>(&q1);
}

__device__ __forceinline__ float sigf(float x) {
    return __fdividef(1.0f, 1.0f + __expf(-x));
}
__device__ __forceinline__ float tanhfast(float x) {
    return __fdividef(2.0f, 1.0f + __expf(-2.0f * x)) - 1.0f;
}

// ================= split pass =================
__global__ __launch_bounds__(256) void split_inputs(
    const float* __restrict__ x,
    const float* __restrict__ wih,
    const float* __restrict__ h0)
{
    if (blockIdx.x == 0 && threadIdx.x < NBLK) g_flags[threadIdx.x] = 0;

    const size_t NX  = (size_t)T_STEPS * BATCH * INDIM / 4;
    const size_t NW  = (size_t)G4 * INDIM / 4;
    const size_t NH0 = (size_t)BATCH * HID / 4;
    const size_t total = NX + NW + NH0;
    for (size_t i = (size_t)blockIdx.x * blockDim.x + threadIdx.x;
         i < total; i += (size_t)gridDim.x * blockDim.x) {
        if (i < NX) {
            float4 v = ((const float4*)x)[i];
            uint2 h, l; split4(v, h, l);
            ((uint2*)g_xhi)[i] = h;
            ((uint2*)g_xlo)[i] = l;
        } else if (i < NX + NW) {
            size_t k = i - NX;
            float4 v = ((const float4*)wih)[k];
            uint2 h, l; split4(v, h, l);
            ((uint2*)g_wihhi)[k] = h;
            ((uint2*)g_wihlo)[k] = l;
        } else {
            size_t e4 = i - NX - NW;
            size_t e  = e4 * 4;
            int b = (int)(e >> 10);
            int kbase = (int)(e & 1023);
            float4 v = ((const float4*)h0)[e4];
            float vv[4] = {v.x, v.y, v.z, v.w};
            int r  = b & 15;
            int rb = b >> 4;
#pragma unroll
            for (int q = 0; q < 4; q++) {
                int k  = kbase + q;
                int kg = k >> 4, kk = k & 15;
                int lanep = ((r & 7) << 2) + ((kk & 7) >> 1);
                int reg   = ((kk >= 8) ? 2 : 0) + ((r >= 8) ? 1 : 0);
                int byte_ = kk & 1;
                __nv_bfloat16 hi = __float2bfloat16_rn(vv[q]);
                __nv_bfloat16 lo = __float2bfloat16_rn(vv[q] - __bfloat162float(hi));
                ((__nv_bfloat16*)&g_hpk[0][0][rb][kg][lanep])[reg * 2 + byte_] = hi;
                ((__nv_bfloat16*)&g_hpk[0][1][rb][kg][lanep])[reg * 2 + byte_] = lo;
            }
        }
    }
}

// ================= x_proj GEMM (unchanged from R8) =================
#define XP_ROWB 144
#define XP_TILE (128 * XP_ROWB)
#define XP_BUF  (4 * XP_TILE)
#define XP_SMEM (2 * XP_BUF)

__global__ __launch_bounds__(256) void xproj_mma(
    const float* __restrict__ bih,
    const float* __restrict__ bhh)
{
    extern __shared__ char smem[];
    const uint32_t sb = smem_u32(smem);
    const int tid  = threadIdx.x;
    const int lane = tid & 31;
    const int w    = tid >> 5;
    const int wm   = w & 1;
    const int wn   = w >> 1;
    const int jb   = blockIdx.x * 32;
    const size_t mb = (size_t)blockIdx.y * 128;

    float acc[4][4][4];
#pragma unroll
    for (int a = 0; a < 4; a++)
#pragma unroll
        for (int b = 0; b < 4; b++)
#pragma unroll
            for (int c = 0; c < 4; c++) acc[a][b][c] = 0.f;

    const int a_row = wm * 64 + (lane & 7) + ((lane >> 3) & 1) * 8;
    const int a_k8  = (lane >> 4) * 8;
    const int b_row = wn * 32 + (lane & 7) + (lane >> 4) * 8;
    const int b_k8  = ((lane >> 3) & 1) * 8;

    int st_row[4], st_c[4], st_wrow[4];
#pragma unroll
    for (int q = 0; q < 4; q++) {
        int s = tid * 4 + q;
        st_row[q]  = s >> 3;
        st_c[q]    = s & 7;
        st_wrow[q] = (st_row[q] & 3) * HID + jb + (st_row[q] >> 2);
    }

    auto stage = [&](int kb, int buf) {
        uint32_t base = sb + buf * XP_BUF;
#pragma unroll
        for (int q = 0; q < 4; q++) {
            size_t gk = (size_t)kb * 64 + st_c[q] * 8;
            uint32_t off = st_row[q] * XP_ROWB + st_c[q] * 16;
            cp16(base + 0 * XP_TILE + off, &g_xhi[(mb + st_row[q]) * INDIM + gk]);
            cp16(base + 1 * XP_TILE + off, &g_xlo[(mb + st_row[q]) * INDIM + gk]);
            cp16(base + 2 * XP_TILE + off, &g_wihhi[(size_t)st_wrow[q] * INDIM + gk]);
            cp16(base + 3 * XP_TILE + off, &g_wihlo[(size_t)st_wrow[q] * INDIM + gk]);
        }
        CP_COMMIT();
    };

    stage(0, 0);

    for (int kb = 0; kb < 8; kb++) {
        const int buf = kb & 1;
        if (kb < 7) stage(kb + 1, buf ^ 1);
        if (kb < 7) { CP_WAIT(1); } else { CP_WAIT(0); }
        __syncthreads();

        const uint32_t aHi = sb + buf * XP_BUF;
        const uint32_t aLo = aHi + XP_TILE;
        const uint32_t bHi = aHi + 2 * XP_TILE;
        const uint32_t bLo = aHi + 3 * XP_TILE;

#pragma unroll
        for (int s = 0; s < 4; s++) {
            uint32_t bh[8], bl[8];
#pragma unroll
            for (int p = 0; p < 2; p++) {
                uint32_t off = (b_row + p * 16) * XP_ROWB + (s * 16 + b_k8) * 2;
                LDSM_X4(bh[p*4+0], bh[p*4+1], bh[p*4+2], bh[p*4+3], bHi + off);
                LDSM_X4(bl[p*4+0], bl[p*4+1], bl[p*4+2], bl[p*4+3], bLo + off);
            }
#pragma unroll
            for (int mt = 0; mt < 4; mt++) {
                uint32_t off = (a_row + mt * 16) * XP_ROWB + (s * 16 + a_k8) * 2;
                uint32_t ah0, ah1, ah2, ah3, al0, al1, al2, al3;
                LDSM_X4(ah0, ah1, ah2, ah3, aHi + off);
                LDSM_X4(al0, al1, al2, al3, aLo + off);
#pragma unroll
                for (int nt = 0; nt < 4; nt++) {
                    float* d = acc[mt][nt];
                    mma_bf16(d[0], d[1], d[2], d[3], ah0, ah1, ah2, ah3, bh[nt*2], bh[nt*2+1]);
                    mma_bf16(d[0], d[1], d[2], d[3], ah0, ah1, ah2, ah3, bl[nt*2], bl[nt*2+1]);
                    mma_bf16(d[0], d[1], d[2], d[3], al0, al1, al2, al3, bh[nt*2], bh[nt*2+1]);
                }
            }
        }
        __syncthreads();
    }

    const int colq = (lane & 3) * 2;
#pragma unroll
    for (int nt = 0; nt < 4; nt++) {
        int nloc = wn * 32 + nt * 8 + colq;
        int g0 = nloc & 3,        j0 = jb + (nloc >> 2);
        int g1 = (nloc + 1) & 3,  j1 = jb + ((nloc + 1) >> 2);
        float bb0 = bih[g0 * HID + j0] + bhh[g0 * HID + j0];
        float bb1 = bih[g1 * HID + j1] + bhh[g1 * HID + j1];
#pragma unroll
        for (int mt = 0; mt < 4; mt++) {
            size_t r0 = mb + wm * 64 + mt * 16 + (lane >> 2);
            float2 v0 = make_float2(acc[mt][nt][0] + bb0, acc[mt][nt][1] + bb1);
            float2 v1 = make_float2(acc[mt][nt][2] + bb0, acc[mt][nt][3] + bb1);
            *(float2*)&g_xproj[r0 * G4 + jb * 4 + nloc]       = v0;
            *(float2*)&g_xproj[(r0 + 8) * G4 + jb * 4 + nloc] = v1;
        }
    }
}

// ================= persistent recurrent kernel (K-split warps) =================
// Warp (mt, ks): batch tile mt, K half ks. Each warp loads DISJOINT A fragments
// (kg in [ks*32, ks*32+32)) for all 32 N-cols; partials combined through smem.
__global__ __launch_bounds__(256, 1) void lstm_rec_pk(
    const float* __restrict__ c0in,
    const float* __restrict__ whh,
    float* __restrict__ out, int out_size)
{
    extern __shared__ char smem[];
    const uint32_t sb = smem_u32(smem);
    const int tid  = threadIdx.x;
    const int lane = tid & 31;
    const int w    = tid >> 5;
    const int mt   = w & 3;            // batch tile
    const int ks   = w >> 2;           // K half
    const int blk  = blockIdx.x;
    const int hb   = blk * 8;
    const int kgc  = blk >> 1;

    // one-time: W slice -> smem (gate-interleaved rows, proven mapping), hi+lo
    for (int it = 0; it < 32; it++) {
        int e4 = it * 256 + tid;
        int n  = e4 >> 8;
        int kf = (e4 & 255) * 4;
        int nh_ = n >> 4, r = n & 15;
        int nt = r >> 3, q = (r & 7) >> 1, low = r & 1;
        int gate = nt * 2 + low, j = 4 * nh_ + q;
        float4 v = *(const float4*)&whh[(size_t)(gate * HID + hb + j) * HID + kf];
        uint2 hp, lp; split4(v, hp, lp);
        *(uint2*)(smem + SM_W + n * WROWB + kf * 2) = hp;
        *(uint2*)(smem + SM_W + WPLANE + n * WROWB + kf * 2) = lp;
    }
    __syncthreads();

    const uint32_t bRow0 = (uint32_t)((lane & 7) + ((lane >> 4) << 3)) * WROWB;
    const uint32_t bRow1 = bRow0 + 16u * WROWB;
    const uint32_t bK8   = ((lane >> 3) & 1) * 8;

    const int b0 = mt * 16 + (lane >> 2);
    const int b1 = b0 + 8;
    const int j0 = lane & 3;
    const int j1 = 4 + j0;
    const int col0 = hb + j0;
    const int col1 = hb + j1;

    // stage offsets per group (packed-h layout math, proven R7/R8)
    const uint32_t off0 = (uint32_t)(mt * 32 + ((lane >> 2) << 2) + (j0 >> 1)) * 8 + (j0 & 1) * 2;
    const uint32_t off1 = (uint32_t)(mt * 32 + ((lane >> 2) << 2) + (j1 >> 1)) * 8 + (j1 & 1) * 2;

    float cst[4] = {0.f, 0.f, 0.f, 0.f};
    if (ks == 0) {
        cst[0] = c0in[b0 * HID + col0];
        cst[1] = c0in[b1 * HID + col0];
        cst[2] = c0in[b0 * HID + col1];
        cst[3] = c0in[b1 * HID + col1];
    }

    float4* red = (float4*)(smem + SM_RED);   // [mt][tile][lane] float4

    for (int t = 0; t < T_STEPS; t++) {
        const int rbuf = t & 1;
        const uint4* __restrict__ Ah = &g_hpk[rbuf][0][mt][ks * 32][lane];
        const uint4* __restrict__ Al = &g_hpk[rbuf][1][mt][ks * 32][lane];

        float4 xg0, xg1, xg2, xg3;
        if (ks == 0) {
            const float* xpb = g_xproj + ((size_t)t * BATCH) * G4;
            xg0 = *(const float4*)(xpb + (size_t)b0 * G4 + col0 * 4);
            xg1 = *(const float4*)(xpb + (size_t)b1 * G4 + col0 * 4);
            xg2 = *(const float4*)(xpb + (size_t)b0 * G4 + col1 * 4);
            xg3 = *(const float4*)(xpb + (size_t)b1 * G4 + col1 * 4);
        }

        float am[4][4], ac[4][4];
#pragma unroll
        for (int tt = 0; tt < 4; tt++)
#pragma unroll
            for (int c = 0; c < 4; c++) { am[tt][c] = 0.f; ac[tt][c] = 0.f; }

        // 16-deep A prefetch (2 phases x 16 kg)
        uint4 pah[16], pal[16];
#pragma unroll
        for (int i = 0; i < 16; i++) { pah[i] = Ah[i * 32]; pal[i] = Al[i * 32]; }

#pragma unroll
        for (int ph = 0; ph < 2; ph++) {
#pragma unroll
            for (int u = 0; u < 16; u++) {
                const int kg  = ph * 16 + u;
                const int kgg = ks * 32 + kg;
                uint32_t ah0 = pah[u].x, ah1 = pah[u].y, ah2 = pah[u].z, ah3 = pah[u].w;
                uint32_t al0 = pal[u].x, al1 = pal[u].y, al2 = pal[u].z, al3 = pal[u].w;
                if (ph == 0) { pah[u] = Ah[(kg + 16) * 32]; pal[u] = Al[(kg + 16) * 32]; }
                uint32_t ko = (uint32_t)((kgg * 16 + bK8) << 1);
                uint32_t bh[8], bl[8];
                LDSM_X4(bh[0], bh[1], bh[2], bh[3], sb + SM_W + bRow0 + ko);
                LDSM_X4(bh[4], bh[5], bh[6], bh[7], sb + SM_W + bRow1 + ko);
                LDSM_X4(bl[0], bl[1], bl[2], bl[3], sb + SM_W + WPLANE + bRow0 + ko);
                LDSM_X4(bl[4], bl[5], bl[6], bl[7], sb + SM_W + WPLANE + bRow1 + ko);
#pragma unroll
                for (int tt = 0; tt < 4; tt++) {
                    mma_bf16(am[tt][0], am[tt][1], am[tt][2], am[tt][3],
                             ah0, ah1, ah2, ah3, bh[tt*2], bh[tt*2+1]);
                    mma_bf16(ac[tt][0], ac[tt][1], ac[tt][2], ac[tt][3],
                             ah0, ah1, ah2, ah3, bl[tt*2], bl[tt*2+1]);
                    mma_bf16(ac[tt][0], ac[tt][1], ac[tt][2], ac[tt][3],
                             al0, al1, al2, al3, bh[tt*2], bh[tt*2+1]);
                }
            }
        }

        // chain sums
        float G[4][4];
#pragma unroll
        for (int tt = 0; tt < 4; tt++)
#pragma unroll
            for (int c = 0; c < 4; c++) G[tt][c] = am[tt][c] + ac[tt][c];

        // exchange partials
        if (ks == 1) {
#pragma unroll
            for (int tt = 0; tt < 4; tt++)
                red[(mt * 4 + tt) * 32 + lane] =
                    make_float4(G[tt][0], G[tt][1], G[tt][2], G[tt][3]);
        }
        __syncthreads();

        float hvv[4];
        if (ks == 0) {
#pragma unroll
            for (int tt = 0; tt < 4; tt++) {
                float4 v = red[(mt * 4 + tt) * 32 + lane];
                G[tt][0] += v.x; G[tt][1] += v.y; G[tt][2] += v.z; G[tt][3] += v.w;
            }
            // group 0 (tiles 0,1): cols col0 ; group 1 (tiles 2,3): cols col1
            float ig, fg, gg, og;
            ig = sigf(G[0][0] + xg0.x); fg = sigf(G[0][1] + xg0.y);
            gg = tanhfast(G[1][0] + xg0.z); og = sigf(G[1][1] + xg0.w);
            cst[0] = fg * cst[0] + ig * gg;  hvv[0] = og * tanhfast(cst[0]);

            ig = sigf(G[0][2] + xg1.x); fg = sigf(G[0][3] + xg1.y);
            gg = tanhfast(G[1][2] + xg1.z); og = sigf(G[1][3] + xg1.w);
            cst[1] = fg * cst[1] + ig * gg;  hvv[1] = og * tanhfast(cst[1]);

            ig = sigf(G[2][0] + xg2.x); fg = sigf(G[2][1] + xg2.y);
            gg = tanhfast(G[3][0] + xg2.z); og = sigf(G[3][1] + xg2.w);
            cst[2] = fg * cst[2] + ig * gg;  hvv[2] = og * tanhfast(cst[2]);

            ig = sigf(G[2][2] + xg3.x); fg = sigf(G[2][3] + xg3.y);
            gg = tanhfast(G[3][2] + xg3.z); og = sigf(G[3][3] + xg3.w);
            cst[3] = fg * cst[3] + ig * gg;  hvv[3] = og * tanhfast(cst[3]);

            // stage packed-h slice
            char* st = smem + SM_STAGE;
            __nv_bfloat16 h0 = __float2bfloat16_rn(hvv[0]);
            __nv_bfloat16 h1 = __float2bfloat16_rn(hvv[1]);
            __nv_bfloat16 h2 = __float2bfloat16_rn(hvv[2]);
            __nv_bfloat16 h3 = __float2bfloat16_rn(hvv[3]);
            *(__nv_bfloat16*)(st + off0)        = h0;
            *(__nv_bfloat16*)(st + off0 + 4)    = h1;
            *(__nv_bfloat16*)(st + off1)        = h2;
            *(__nv_bfloat16*)(st + off1 + 4)    = h3;
            *(__nv_bfloat16*)(st + off0 + 1024) = __float2bfloat16_rn(hvv[0] - __bfloat162float(h0));
            *(__nv_bfloat16*)(st + off0 + 1028) = __float2bfloat16_rn(hvv[1] - __bfloat162float(h1));
            *(__nv_bfloat16*)(st + off1 + 1024) = __float2bfloat16_rn(hvv[2] - __bfloat162float(h2));
            *(__nv_bfloat16*)(st + off1 + 1028) = __float2bfloat16_rn(hvv[3] - __bfloat162float(h3));
        }
        __syncthreads();

        // coalesced packed writeback: 256 threads, one STG.64 each
        {
            const int wbuf = (t + 1) & 1;
            int plane = tid >> 7, rb = (tid >> 5) & 3, lt = tid & 31;
            uint2 v = *(uint2*)(smem + SM_STAGE + (uint32_t)((plane * 4 + rb) * 32 + lt) * 8);
            uint2* dst = (uint2*)&g_hpk[wbuf][plane][rb][kgc][lt];
            dst[blk & 1] = v;
        }

        if (t == T_STEPS - 1) {
            if (ks == 0) {
                out[((size_t)t * BATCH + b0) * HID + col0] = hvv[0];
                out[((size_t)t * BATCH + b1) * HID + col0] = hvv[1];
                out[((size_t)t * BATCH + b0) * HID + col1] = hvv[2];
                out[((size_t)t * BATCH + b1) * HID + col1] = hvv[3];
                const long long need = (long long)T_STEPS * BATCH * HID + 2LL * BATCH * HID;
                if ((long long)out_size >= need) {
                    size_t base = (size_t)T_STEPS * BATCH * HID;
                    out[base + (size_t)b0 * HID + col0] = hvv[0];
                    out[base + (size_t)b1 * HID + col0] = hvv[1];
                    out[base + (size_t)b0 * HID + col1] = hvv[2];
                    out[base + (size_t)b1 * HID + col1] = hvv[3];
                    size_t cb = base + (size_t)BATCH * HID;
                    out[cb + (size_t)b0 * HID + col0] = cst[0];
                    out[cb + (size_t)b1 * HID + col0] = cst[1];
                    out[cb + (size_t)b0 * HID + col1] = cst[2];
                    out[cb + (size_t)b1 * HID + col1] = cst[3];
                }
            }
        } else {
            __threadfence();           // release packed-h stores
            __syncthreads();
            if (tid == 0) ((volatile int*)g_flags)[blk] = t + 1;
            if (ks == 0) {             // out stores off the critical path
                out[((size_t)t * BATCH + b0) * HID + col0] = hvv[0];
                out[((size_t)t * BATCH + b1) * HID + col0] = hvv[1];
                out[((size_t)t * BATCH + b0) * HID + col1] = hvv[2];
                out[((size_t)t * BATCH + b1) * HID + col1] = hvv[3];
            }
            if (tid < NBLK) {
                while (((volatile int*)g_flags)[tid] < t + 1) { __nanosleep(32); }
            }
            __threadfence();           // acquire + invalidate L1 before new h reads
            __syncthreads();
        }
    }
}

// ================= launch =================
extern "C" void kernel_launch(void* const* d_in, const int* in_sizes, int n_in,
                              void* d_out, int out_size) {
    const float* x    = (const float*)d_in[0];
    const float* h0   = (const float*)d_in[1];
    const float* c0   = (const float*)d_in[2];
    const float* w_ih = (const float*)d_in[3];
    const float* w_hh = (const float*)d_in[4];
    const float* b_ih = (const float*)d_in[5];
    const float* b_hh = (const float*)d_in[6];
    float* out = (float*)d_out;

    cudaFuncSetAttribute(xproj_mma,
                         cudaFuncAttributeMaxDynamicSharedMemorySize, XP_SMEM);
    cudaFuncSetAttribute(lstm_rec_pk,
                         cudaFuncAttributeMaxDynamicSharedMemorySize, R_SMEM);

    split_inputs<<<2048, 256>>>(x, w_ih, h0);
    dim3 gx(G4 / 128, (T_STEPS * BATCH) / 128);   // 32 x 512
    xproj_mma<<<gx, 256, XP_SMEM>>>(b_ih, b_hh);
    lstm_rec_pk<<<NBLK, 256, R_SMEM>>>(c0, w_hh, out, out_size);
}

// round 10
// speedup vs baseline: 1.6703x; 1.0765x over previous
#include <cuda_runtime.h>
#include <cuda_bf16.h>
#include <math.h>
#include <stdint.h>

#define T_STEPS 1024
#define BATCH   64
#define INDIM   512
#define HID     1024
#define G4      4096

#define NBLK 128

// W-resident smem geometry (proven R6-R9)
#define WROWB   2064                 // 1032 bf16 per W row (1024 + 8 pad)
#define WPLANE  (32 * WROWB)         // 66048
#define SM_W    0
#define SM_STAGE (2 * WPLANE)        // 132096
#define SM_RED  (SM_STAGE + 2048)    // 134144 ; 24KB partial-sum exchange
#define R_SMEM  (SM_RED + 24576)     // 158720

// ---------------- device scratch (static) ----------------
__device__ float          g_xproj[(size_t)T_STEPS * BATCH * G4];   // [t][b][j*4+gate]
__device__ __nv_bfloat16  g_xhi[(size_t)T_STEPS * BATCH * INDIM];
__device__ __nv_bfloat16  g_xlo[(size_t)T_STEPS * BATCH * INDIM];
__device__ __nv_bfloat16  g_wihhi[(size_t)G4 * INDIM];
__device__ __nv_bfloat16  g_wihlo[(size_t)G4 * INDIM];
// h packed in m16n8k16 A-fragment order: [buf][plane hi/lo][rb=b>>4][kg=k>>4][lane] = uint4
__device__ uint4          g_hpk[2][2][4][64][32];
__device__ int            g_flags[NBLK];

// ---------------- helpers ----------------
__device__ __forceinline__ uint32_t smem_u32(const void* p) {
    uint32_t a;
    asm("{ .reg .u64 t; cvta.to.shared.u64 t, %1; cvt.u32.u64 %0, t; }" : "=r"(a) : "l"(p));
    return a;
}

#define LDSM_X4(r0,r1,r2,r3,addr) \
    asm volatile("ldmatrix.sync.aligned.m8n8.x4.shared.b16 {%0,%1,%2,%3}, [%4];" \
                 : "=r"(r0), "=r"(r1), "=r"(r2), "=r"(r3) : "r"(addr))

__device__ __forceinline__ void mma_bf16(float& d0, float& d1, float& d2, float& d3,
                                         uint32_t a0, uint32_t a1, uint32_t a2, uint32_t a3,
                                         uint32_t b0, uint32_t b1) {
    asm volatile(
        "mma.sync.aligned.m16n8k16.row.col.f32.bf16.bf16.f32 "
        "{%0,%1,%2,%3}, {%4,%5,%6,%7}, {%8,%9}, {%0,%1,%2,%3};"
        : "+f"(d0), "+f"(d1), "+f"(d2), "+f"(d3)
        : "r"(a0), "r"(a1), "r"(a2), "r"(a3), "r"(b0), "r"(b1));
}

__device__ __forceinline__ void cp16(uint32_t dst, const void* src) {
    asm volatile("cp.async.cg.shared.global [%0], [%1], 16;" :: "r"(dst), "l"(src) : "memory");
}
#define CP_COMMIT() asm volatile("cp.async.commit_group;" ::: "memory")
#define CP_WAIT(n)  asm volatile("cp.async.wait_group %0;" :: "n"(n) : "memory")

__device__ __forceinline__ void split4(float4 v, uint2& hip, uint2& lop) {
    __nv_bfloat16 hx = __float2bfloat16_rn(v.x);
    __nv_bfloat16 hy = __float2bfloat16_rn(v.y);
    __nv_bfloat16 hz = __float2bfloat16_rn(v.z);
    __nv_bfloat16 hw = __float2bfloat16_rn(v.w);
    __nv_bfloat162 p0 = __halves2bfloat162(hx, hy);
    __nv_bfloat162 p1 = __halves2bfloat162(hz, hw);
    hip.x = *reinterpret_cast<unsigned*>(&p0);
    hip.y = *reinterpret_cast<unsigned*>(&p1);
    __nv_bfloat162 q0 = __floats2bfloat162_rn(v.x - __bfloat162float(hx),
                                              v.y - __bfloat162float(hy));
    __nv_bfloat162 q1 = __floats2bfloat162_rn(v.z - __bfloat162float(hz),
                                              v.w - __bfloat162float(hw));
    lop.x = *reinterpret_cast<unsigned*>(&q0);
    lop.y = *reinterpret_cast<unsigned*>(&q1);
}

__device__ __forceinline__ float sigf(float x) {
    return __fdividef(1.0f, 1.0f + __expf(-x));
}
__device__ __forceinline__ float tanhfast(float x) {
    return __fdividef(2.0f, 1.0f + __expf(-2.0f * x)) - 1.0f;
}

// ================= split pass =================
__global__ __launch_bounds__(256) void split_inputs(
    const float* __restrict__ x,
    const float* __restrict__ wih,
    const float* __restrict__ h0)
{
    if (blockIdx.x == 0 && threadIdx.x < NBLK) g_flags[threadIdx.x] = 0;

    const size_t NX  = (size_t)T_STEPS * BATCH * INDIM / 4;
    const size_t NW  = (size_t)G4 * INDIM / 4;
    const size_t NH0 = (size_t)BATCH * HID / 4;
    const size_t total = NX + NW + NH0;
    for (size_t i = (size_t)blockIdx.x * blockDim.x + threadIdx.x;
         i < total; i += (size_t)gridDim.x * blockDim.x) {
        if (i < NX) {
            float4 v = ((const float4*)x)[i];
            uint2 h, l; split4(v, h, l);
            ((uint2*)g_xhi)[i] = h;
            ((uint2*)g_xlo)[i] = l;
        } else if (i < NX + NW) {
            size_t k = i - NX;
            float4 v = ((const float4*)wih)[k];
            uint2 h, l; split4(v, h, l);
            ((uint2*)g_wihhi)[k] = h;
            ((uint2*)g_wihlo)[k] = l;
        } else {
            size_t e4 = i - NX - NW;
            size_t e  = e4 * 4;
            int b = (int)(e >> 10);
            int kbase = (int)(e & 1023);
            float4 v = ((const float4*)h0)[e4];
            float vv[4] = {v.x, v.y, v.z, v.w};
            int r  = b & 15;
            int rb = b >> 4;
#pragma unroll
            for (int q = 0; q < 4; q++) {
                int k  = kbase + q;
                int kg = k >> 4, kk = k & 15;
                int lanep = ((r & 7) << 2) + ((kk & 7) >> 1);
                int reg   = ((kk >= 8) ? 2 : 0) + ((r >= 8) ? 1 : 0);
                int byte_ = kk & 1;
                __nv_bfloat16 hi = __float2bfloat16_rn(vv[q]);
                __nv_bfloat16 lo = __float2bfloat16_rn(vv[q] - __bfloat162float(hi));
                ((__nv_bfloat16*)&g_hpk[0][0][rb][kg][lanep])[reg * 2 + byte_] = hi;
                ((__nv_bfloat16*)&g_hpk[0][1][rb][kg][lanep])[reg * 2 + byte_] = lo;
            }
        }
    }
}

// ================= x_proj GEMM (unchanged from R8/R9) =================
#define XP_ROWB 144
#define XP_TILE (128 * XP_ROWB)
#define XP_BUF  (4 * XP_TILE)
#define XP_SMEM (2 * XP_BUF)

__global__ __launch_bounds__(256) void xproj_mma(
    const float* __restrict__ bih,
    const float* __restrict__ bhh)
{
    extern __shared__ char smem[];
    const uint32_t sb = smem_u32(smem);
    const int tid  = threadIdx.x;
    const int lane = tid & 31;
    const int w    = tid >> 5;
    const int wm   = w & 1;
    const int wn   = w >> 1;
    const int jb   = blockIdx.x * 32;
    const size_t mb = (size_t)blockIdx.y * 128;

    float acc[4][4][4];
#pragma unroll
    for (int a = 0; a < 4; a++)
#pragma unroll
        for (int b = 0; b < 4; b++)
#pragma unroll
            for (int c = 0; c < 4; c++) acc[a][b][c] = 0.f;

    const int a_row = wm * 64 + (lane & 7) + ((lane >> 3) & 1) * 8;
    const int a_k8  = (lane >> 4) * 8;
    const int b_row = wn * 32 + (lane & 7) + (lane >> 4) * 8;
    const int b_k8  = ((lane >> 3) & 1) * 8;

    int st_row[4], st_c[4], st_wrow[4];
#pragma unroll
    for (int q = 0; q < 4; q++) {
        int s = tid * 4 + q;
        st_row[q]  = s >> 3;
        st_c[q]    = s & 7;
        st_wrow[q] = (st_row[q] & 3) * HID + jb + (st_row[q] >> 2);
    }

    auto stage = [&](int kb, int buf) {
        uint32_t base = sb + buf * XP_BUF;
#pragma unroll
        for (int q = 0; q < 4; q++) {
            size_t gk = (size_t)kb * 64 + st_c[q] * 8;
            uint32_t off = st_row[q] * XP_ROWB + st_c[q] * 16;
            cp16(base + 0 * XP_TILE + off, &g_xhi[(mb + st_row[q]) * INDIM + gk]);
            cp16(base + 1 * XP_TILE + off, &g_xlo[(mb + st_row[q]) * INDIM + gk]);
            cp16(base + 2 * XP_TILE + off, &g_wihhi[(size_t)st_wrow[q] * INDIM + gk]);
            cp16(base + 3 * XP_TILE + off, &g_wihlo[(size_t)st_wrow[q] * INDIM + gk]);
        }
        CP_COMMIT();
    };

    stage(0, 0);

    for (int kb = 0; kb < 8; kb++) {
        const int buf = kb & 1;
        if (kb < 7) stage(kb + 1, buf ^ 1);
        if (kb < 7) { CP_WAIT(1); } else { CP_WAIT(0); }
        __syncthreads();

        const uint32_t aHi = sb + buf * XP_BUF;
        const uint32_t aLo = aHi + XP_TILE;
        const uint32_t bHi = aHi + 2 * XP_TILE;
        const uint32_t bLo = aHi + 3 * XP_TILE;

#pragma unroll
        for (int s = 0; s < 4; s++) {
            uint32_t bh[8], bl[8];
#pragma unroll
            for (int p = 0; p < 2; p++) {
                uint32_t off = (b_row + p * 16) * XP_ROWB + (s * 16 + b_k8) * 2;
                LDSM_X4(bh[p*4+0], bh[p*4+1], bh[p*4+2], bh[p*4+3], bHi + off);
                LDSM_X4(bl[p*4+0], bl[p*4+1], bl[p*4+2], bl[p*4+3], bLo + off);
            }
#pragma unroll
            for (int mt = 0; mt < 4; mt++) {
                uint32_t off = (a_row + mt * 16) * XP_ROWB + (s * 16 + a_k8) * 2;
                uint32_t ah0, ah1, ah2, ah3, al0, al1, al2, al3;
                LDSM_X4(ah0, ah1, ah2, ah3, aHi + off);
                LDSM_X4(al0, al1, al2, al3, aLo + off);
#pragma unroll
                for (int nt = 0; nt < 4; nt++) {
                    float* d = acc[mt][nt];
                    mma_bf16(d[0], d[1], d[2], d[3], ah0, ah1, ah2, ah3, bh[nt*2], bh[nt*2+1]);
                    mma_bf16(d[0], d[1], d[2], d[3], ah0, ah1, ah2, ah3, bl[nt*2], bl[nt*2+1]);
                    mma_bf16(d[0], d[1], d[2], d[3], al0, al1, al2, al3, bh[nt*2], bh[nt*2+1]);
                }
            }
        }
        __syncthreads();
    }

    const int colq = (lane & 3) * 2;
#pragma unroll
    for (int nt = 0; nt < 4; nt++) {
        int nloc = wn * 32 + nt * 8 + colq;
        int g0 = nloc & 3,        j0 = jb + (nloc >> 2);
        int g1 = (nloc + 1) & 3,  j1 = jb + ((nloc + 1) >> 2);
        float bb0 = bih[g0 * HID + j0] + bhh[g0 * HID + j0];
        float bb1 = bih[g1 * HID + j1] + bhh[g1 * HID + j1];
#pragma unroll
        for (int mt = 0; mt < 4; mt++) {
            size_t r0 = mb + wm * 64 + mt * 16 + (lane >> 2);
            float2 v0 = make_float2(acc[mt][nt][0] + bb0, acc[mt][nt][1] + bb1);
            float2 v1 = make_float2(acc[mt][nt][2] + bb0, acc[mt][nt][3] + bb1);
            *(float2*)&g_xproj[r0 * G4 + jb * 4 + nloc]       = v0;
            *(float2*)&g_xproj[(r0 + 8) * G4 + jb * 4 + nloc] = v1;
        }
    }
}

// ================= persistent recurrent kernel (M2xK4 warp split) =================
// Warp (mtp, ks): m-tiles {2mtp, 2mtp+1}, all 32 N-cols, kg in [16ks, 16ks+16).
// One B-fragment set feeds 2 m-tiles (W LDSM dup 4x -> 2x). A loads disjoint, __ldcg.
// 4-way K reduction via smem; cell update spread over warps ks<2 (one mt each).
__global__ __launch_bounds__(256, 1) void lstm_rec_pk(
    const float* __restrict__ c0in,
    const float* __restrict__ whh,
    float* __restrict__ out, int out_size)
{
    extern __shared__ char smem[];
    const uint32_t sb = smem_u32(smem);
    const int tid  = threadIdx.x;
    const int lane = tid & 31;
    const int w    = tid >> 5;
    const int mtp  = w & 1;            // m pair
    const int ks   = w >> 1;           // K quarter
    const int blk  = blockIdx.x;
    const int hb   = blk * 8;
    const int kgc  = blk >> 1;

    // one-time: W slice -> smem (gate-interleaved rows, proven mapping), hi+lo
    for (int it = 0; it < 32; it++) {
        int e4 = it * 256 + tid;
        int n  = e4 >> 8;
        int kf = (e4 & 255) * 4;
        int nh_ = n >> 4, r = n & 15;
        int nt = r >> 3, q = (r & 7) >> 1, low = r & 1;
        int gate = nt * 2 + low, j = 4 * nh_ + q;
        float4 v = *(const float4*)&whh[(size_t)(gate * HID + hb + j) * HID + kf];
        uint2 hp, lp; split4(v, hp, lp);
        *(uint2*)(smem + SM_W + n * WROWB + kf * 2) = hp;
        *(uint2*)(smem + SM_W + WPLANE + n * WROWB + kf * 2) = lp;
    }
    __syncthreads();

    const uint32_t bRow0 = (uint32_t)((lane & 7) + ((lane >> 4) << 3)) * WROWB;
    const uint32_t bRow1 = bRow0 + 16u * WROWB;
    const uint32_t bK8   = ((lane >> 3) & 1) * 8;

    const int j0 = lane & 3;
    const int j1 = 4 + j0;
    const int col0 = hb + j0;
    const int col1 = hb + j1;

    // cell role: warps ks<2 handle mt = 2*mtp + ks
    const int cmt = 2 * mtp + ks;                 // valid when ks<2
    const int cb0 = cmt * 16 + (lane >> 2);
    const int cb1 = cb0 + 8;
    const uint32_t off0 = (uint32_t)(cmt * 32 + ((lane >> 2) << 2) + (j0 >> 1)) * 8 + (j0 & 1) * 2;
    const uint32_t off1 = (uint32_t)(cmt * 32 + ((lane >> 2) << 2) + (j1 >> 1)) * 8 + (j1 & 1) * 2;

    float cst[4] = {0.f, 0.f, 0.f, 0.f};
    if (ks < 2) {
        cst[0] = c0in[cb0 * HID + col0];
        cst[1] = c0in[cb1 * HID + col0];
        cst[2] = c0in[cb0 * HID + col1];
        cst[3] = c0in[cb1 * HID + col1];
    }

    float4* red = (float4*)(smem + SM_RED);   // [src(3)][mtp(2)][mti(2)][tt(4)][lane]

    for (int t = 0; t < T_STEPS; t++) {
        const int rbuf = t & 1;
        const uint4* __restrict__ Ahp[2];
        const uint4* __restrict__ Alp[2];
#pragma unroll
        for (int mti = 0; mti < 2; mti++) {
            Ahp[mti] = &g_hpk[rbuf][0][2 * mtp + mti][ks * 16][lane];
            Alp[mti] = &g_hpk[rbuf][1][2 * mtp + mti][ks * 16][lane];
        }

        // 6-deep A prefetch per m-tile (24 outstanding uint4/thread)
        uint4 pah[6][2], pal[6][2];
#pragma unroll
        for (int i = 0; i < 6; i++)
#pragma unroll
            for (int mti = 0; mti < 2; mti++) {
                pah[i][mti] = __ldcg(&Ahp[mti][i * 32]);
                pal[i][mti] = __ldcg(&Alp[mti][i * 32]);
            }

        // xg prefetch (cell warps only), after A-loads are in flight
        float4 xg0, xg1, xg2, xg3;
        if (ks < 2) {
            const float* xpb = g_xproj + ((size_t)t * BATCH) * G4;
            xg0 = *(const float4*)(xpb + (size_t)cb0 * G4 + col0 * 4);
            xg1 = *(const float4*)(xpb + (size_t)cb1 * G4 + col0 * 4);
            xg2 = *(const float4*)(xpb + (size_t)cb0 * G4 + col1 * 4);
            xg3 = *(const float4*)(xpb + (size_t)cb1 * G4 + col1 * 4);
        }

        float am[2][4][4], ac[2][4][4];
#pragma unroll
        for (int mti = 0; mti < 2; mti++)
#pragma unroll
            for (int tt = 0; tt < 4; tt++)
#pragma unroll
                for (int c = 0; c < 4; c++) { am[mti][tt][c] = 0.f; ac[mti][tt][c] = 0.f; }

#pragma unroll
        for (int kg = 0; kg < 16; kg++) {
            const int slot = kg % 6;
            uint4 vh[2], vl[2];
#pragma unroll
            for (int mti = 0; mti < 2; mti++) { vh[mti] = pah[slot][mti]; vl[mti] = pal[slot][mti]; }
            if (kg + 6 < 16) {
#pragma unroll
                for (int mti = 0; mti < 2; mti++) {
                    pah[slot][mti] = __ldcg(&Ahp[mti][(kg + 6) * 32]);
                    pal[slot][mti] = __ldcg(&Alp[mti][(kg + 6) * 32]);
                }
            }
            const int kgg = ks * 16 + kg;
            const uint32_t ko = (uint32_t)((kgg * 16 + bK8) << 1);
            uint32_t bh[8], bl[8];
            LDSM_X4(bh[0], bh[1], bh[2], bh[3], sb + SM_W + bRow0 + ko);
            LDSM_X4(bh[4], bh[5], bh[6], bh[7], sb + SM_W + bRow1 + ko);
            LDSM_X4(bl[0], bl[1], bl[2], bl[3], sb + SM_W + WPLANE + bRow0 + ko);
            LDSM_X4(bl[4], bl[5], bl[6], bl[7], sb + SM_W + WPLANE + bRow1 + ko);
            // pass 1: hi * Whi (main)
#pragma unroll
            for (int mti = 0; mti < 2; mti++)
#pragma unroll
                for (int tt = 0; tt < 4; tt++)
                    mma_bf16(am[mti][tt][0], am[mti][tt][1], am[mti][tt][2], am[mti][tt][3],
                             vh[mti].x, vh[mti].y, vh[mti].z, vh[mti].w, bh[tt*2], bh[tt*2+1]);
            // pass 2: hi * Wlo
#pragma unroll
            for (int mti = 0; mti < 2; mti++)
#pragma unroll
                for (int tt = 0; tt < 4; tt++)
                    mma_bf16(ac[mti][tt][0], ac[mti][tt][1], ac[mti][tt][2], ac[mti][tt][3],
                             vh[mti].x, vh[mti].y, vh[mti].z, vh[mti].w, bl[tt*2], bl[tt*2+1]);
            // pass 3: lo * Whi
#pragma unroll
            for (int mti = 0; mti < 2; mti++)
#pragma unroll
                for (int tt = 0; tt < 4; tt++)
                    mma_bf16(ac[mti][tt][0], ac[mti][tt][1], ac[mti][tt][2], ac[mti][tt][3],
                             vl[mti].x, vl[mti].y, vl[mti].z, vl[mti].w, bh[tt*2], bh[tt*2+1]);
        }

        // chain sums into am
#pragma unroll
        for (int mti = 0; mti < 2; mti++)
#pragma unroll
            for (int tt = 0; tt < 4; tt++)
#pragma unroll
                for (int c = 0; c < 4; c++) am[mti][tt][c] += ac[mti][tt][c];

        // write partials for mti's handled by other cell warps
        {
            const int src = (ks < 2) ? 0 : ks - 1;
#pragma unroll
            for (int mti = 0; mti < 2; mti++) {
                if (ks != mti) {
                    int base = ((src * 2 + mtp) * 2 + mti) * 4;
#pragma unroll
                    for (int tt = 0; tt < 4; tt++)
                        red[(base + tt) * 32 + lane] =
                            make_float4(am[mti][tt][0], am[mti][tt][1],
                                        am[mti][tt][2], am[mti][tt][3]);
                }
            }
        }
        __syncthreads();

        float hvv[4];
        if (ks < 2) {
            const int mti = ks;
#pragma unroll
            for (int src = 0; src < 3; src++) {
                int base = ((src * 2 + mtp) * 2 + mti) * 4;
#pragma unroll
                for (int tt = 0; tt < 4; tt++) {
                    float4 v = red[(base + tt) * 32 + lane];
                    am[mti][tt][0] += v.x; am[mti][tt][1] += v.y;
                    am[mti][tt][2] += v.z; am[mti][tt][3] += v.w;
                }
            }
            float (*G)[4] = am[mti];
            float ig, fg, gg, og;
            ig = sigf(G[0][0] + xg0.x); fg = sigf(G[0][1] + xg0.y);
            gg = tanhfast(G[1][0] + xg0.z); og = sigf(G[1][1] + xg0.w);
            cst[0] = fg * cst[0] + ig * gg;  hvv[0] = og * tanhfast(cst[0]);

            ig = sigf(G[0][2] + xg1.x); fg = sigf(G[0][3] + xg1.y);
            gg = tanhfast(G[1][2] + xg1.z); og = sigf(G[1][3] + xg1.w);
            cst[1] = fg * cst[1] + ig * gg;  hvv[1] = og * tanhfast(cst[1]);

            ig = sigf(G[2][0] + xg2.x); fg = sigf(G[2][1] + xg2.y);
            gg = tanhfast(G[3][0] + xg2.z); og = sigf(G[3][1] + xg2.w);
            cst[2] = fg * cst[2] + ig * gg;  hvv[2] = og * tanhfast(cst[2]);

            ig = sigf(G[2][2] + xg3.x); fg = sigf(G[2][3] + xg3.y);
            gg = tanhfast(G[3][2] + xg3.z); og = sigf(G[3][3] + xg3.w);
            cst[3] = fg * cst[3] + ig * gg;  hvv[3] = og * tanhfast(cst[3]);

            // stage packed-h slice
            char* st = smem + SM_STAGE;
            __nv_bfloat16 h0 = __float2bfloat16_rn(hvv[0]);
            __nv_bfloat16 h1 = __float2bfloat16_rn(hvv[1]);
            __nv_bfloat16 h2 = __float2bfloat16_rn(hvv[2]);
            __nv_bfloat16 h3 = __float2bfloat16_rn(hvv[3]);
            *(__nv_bfloat16*)(st + off0)        = h0;
            *(__nv_bfloat16*)(st + off0 + 4)    = h1;
            *(__nv_bfloat16*)(st + off1)        = h2;
            *(__nv_bfloat16*)(st + off1 + 4)    = h3;
            *(__nv_bfloat16*)(st + off0 + 1024) = __float2bfloat16_rn(hvv[0] - __bfloat162float(h0));
            *(__nv_bfloat16*)(st + off0 + 1028) = __float2bfloat16_rn(hvv[1] - __bfloat162float(h1));
            *(__nv_bfloat16*)(st + off1 + 1024) = __float2bfloat16_rn(hvv[2] - __bfloat162float(h2));
            *(__nv_bfloat16*)(st + off1 + 1028) = __float2bfloat16_rn(hvv[3] - __bfloat162float(h3));
        }
        __syncthreads();

        // coalesced packed writeback: 256 threads, one STG.64 each
        {
            const int wbuf = (t + 1) & 1;
            int plane = tid >> 7, rb = (tid >> 5) & 3, lt = tid & 31;
            uint2 v = *(uint2*)(smem + SM_STAGE + (uint32_t)((plane * 4 + rb) * 32 + lt) * 8);
            uint2* dst = (uint2*)&g_hpk[wbuf][plane][rb][kgc][lt];
            dst[blk & 1] = v;
        }

        if (t == T_STEPS - 1) {
            if (ks < 2) {
                out[((size_t)t * BATCH + cb0) * HID + col0] = hvv[0];
                out[((size_t)t * BATCH + cb1) * HID + col0] = hvv[1];
                out[((size_t)t * BATCH + cb0) * HID + col1] = hvv[2];
                out[((size_t)t * BATCH + cb1) * HID + col1] = hvv[3];
                const long long need = (long long)T_STEPS * BATCH * HID + 2LL * BATCH * HID;
                if ((long long)out_size >= need) {
                    size_t base = (size_t)T_STEPS * BATCH * HID;
                    out[base + (size_t)cb0 * HID + col0] = hvv[0];
                    out[base + (size_t)cb1 * HID + col0] = hvv[1];
                    out[base + (size_t)cb0 * HID + col1] = hvv[2];
                    out[base + (size_t)cb1 * HID + col1] = hvv[3];
                    size_t cb = base + (size_t)BATCH * HID;
                    out[cb + (size_t)cb0 * HID + col0] = cst[0];
                    out[cb + (size_t)cb1 * HID + col0] = cst[1];
                    out[cb + (size_t)cb0 * HID + col1] = cst[2];
                    out[cb + (size_t)cb1 * HID + col1] = cst[3];
                }
            }
        } else {
            __threadfence();           // release packed-h stores
            __syncthreads();
            if (tid == 0) ((volatile int*)g_flags)[blk] = t + 1;
            if (ks < 2) {              // out stores off the critical path
                out[((size_t)t * BATCH + cb0) * HID + col0] = hvv[0];
                out[((size_t)t * BATCH + cb1) * HID + col0] = hvv[1];
                out[((size_t)t * BATCH + cb0) * HID + col1] = hvv[2];
                out[((size_t)t * BATCH + cb1) * HID + col1] = hvv[3];
            }
            if (tid < NBLK) {
                while (((volatile int*)g_flags)[tid] < t + 1) { __nanosleep(32); }
            }
            __threadfence();           // acquire before new h reads
            __syncthreads();
        }
    }
}

// ================= launch =================
extern "C" void kernel_launch(void* const* d_in, const int* in_sizes, int n_in,
                              void* d_out, int out_size) {
    const float* x    = (const float*)d_in[0];
    const float* h0   = (const float*)d_in[1];
    const float* c0   = (const float*)d_in[2];
    const float* w_ih = (const float*)d_in[3];
    const float* w_hh = (const float*)d_in[4];
    const float* b_ih = (const float*)d_in[5];
    const float* b_hh = (const float*)d_in[6];
    float* out = (float*)d_out;

    cudaFuncSetAttribute(xproj_mma,
                         cudaFuncAttributeMaxDynamicSharedMemorySize, XP_SMEM);
    cudaFuncSetAttribute(lstm_rec_pk,
                         cudaFuncAttributeMaxDynamicSharedMemorySize, R_SMEM);

    split_inputs<<<2048, 256>>>(x, w_ih, h0);
    dim3 gx(G4 / 128, (T_STEPS * BATCH) / 128);   // 32 x 512
    xproj_mma<<<gx, 256, XP_SMEM>>>(b_ih, b_hh);
    lstm_rec_pk<<<NBLK, 256, R_SMEM>>>(c0, w_hh, out, out_size);
}

// round 11
// speedup vs baseline: 2.0278x; 1.2140x over previous
#include <cuda_runtime.h>
#include <cuda_bf16.h>
#include <math.h>
#include <stdint.h>

#define T_STEPS 1024
#define BATCH   64
#define INDIM   512
#define HID     1024
#define G4      4096

#define NBLK 128

// W-resident smem geometry (proven R6-R10)
#define WROWB   2064                 // 1032 bf16 per W row (1024 + 8 pad)
#define WPLANE  (32 * WROWB)         // 66048
#define SM_W    0
#define SM_STAGE (2 * WPLANE)        // 132096
#define SM_RED  (SM_STAGE + 2048)    // 134144 ; 24KB partial-sum exchange
#define R_SMEM  (SM_RED + 24576)     // 158720

// ---------------- device scratch (static) ----------------
__device__ float          g_xproj[(size_t)T_STEPS * BATCH * G4];   // [t][b][j*4+gate]
__device__ __nv_bfloat16  g_xhi[(size_t)T_STEPS * BATCH * INDIM];
__device__ __nv_bfloat16  g_xlo[(size_t)T_STEPS * BATCH * INDIM];
__device__ __nv_bfloat16  g_wihhi[(size_t)G4 * INDIM];
__device__ __nv_bfloat16  g_wihlo[(size_t)G4 * INDIM];
// h packed in m16n8k16 A-fragment order: [buf][plane hi/lo][rb=b>>4][kg=k>>4][lane] = uint4
__device__ uint4          g_hpk[2][2][4][64][32];
__device__ int            g_flags[NBLK];

// ---------------- helpers ----------------
__device__ __forceinline__ uint32_t smem_u32(const void* p) {
    uint32_t a;
    asm("{ .reg .u64 t; cvta.to.shared.u64 t, %1; cvt.u32.u64 %0, t; }" : "=r"(a) : "l"(p));
    return a;
}

#define LDSM_X4(r0,r1,r2,r3,addr) \
    asm volatile("ldmatrix.sync.aligned.m8n8.x4.shared.b16 {%0,%1,%2,%3}, [%4];" \
                 : "=r"(r0), "=r"(r1), "=r"(r2), "=r"(r3) : "r"(addr))

__device__ __forceinline__ void mma_bf16(float& d0, float& d1, float& d2, float& d3,
                                         uint32_t a0, uint32_t a1, uint32_t a2, uint32_t a3,
                                         uint32_t b0, uint32_t b1) {
    asm volatile(
        "mma.sync.aligned.m16n8k16.row.col.f32.bf16.bf16.f32 "
        "{%0,%1,%2,%3}, {%4,%5,%6,%7}, {%8,%9}, {%0,%1,%2,%3};"
        : "+f"(d0), "+f"(d1), "+f"(d2), "+f"(d3)
        : "r"(a0), "r"(a1), "r"(a2), "r"(a3), "r"(b0), "r"(b1));
}

__device__ __forceinline__ void cp16(uint32_t dst, const void* src) {
    asm volatile("cp.async.cg.shared.global [%0], [%1], 16;" :: "r"(dst), "l"(src) : "memory");
}
#define CP_COMMIT() asm volatile("cp.async.commit_group;" ::: "memory")
#define CP_WAIT(n)  asm volatile("cp.async.wait_group %0;" :: "n"(n) : "memory")

// release/acquire flag ops (no MEMBAR.ALL, no CCTL.IVALL L1 flush)
__device__ __forceinline__ void st_rel(int* p, int v) {
    asm volatile("st.release.gpu.global.s32 [%0], %1;" :: "l"(p), "r"(v) : "memory");
}
__device__ __forceinline__ int ld_acq(const int* p) {
    int v;
    asm volatile("ld.acquire.gpu.global.s32 %0, [%1];" : "=r"(v) : "l"(p) : "memory");
    return v;
}

__device__ __forceinline__ void split4(float4 v, uint2& hip, uint2& lop) {
    __nv_bfloat16 hx = __float2bfloat16_rn(v.x);
    __nv_bfloat16 hy = __float2bfloat16_rn(v.y);
    __nv_bfloat16 hz = __float2bfloat16_rn(v.z);
    __nv_bfloat16 hw = __float2bfloat16_rn(v.w);
    __nv_bfloat162 p0 = __halves2bfloat162(hx, hy);
    __nv_bfloat162 p1 = __halves2bfloat162(hz, hw);
    hip.x = *reinterpret_cast<unsigned*>(&p0);
    hip.y = *reinterpret_cast<unsigned*>(&p1);
    __nv_bfloat162 q0 = __floats2bfloat162_rn(v.x - __bfloat162float(hx),
                                              v.y - __bfloat162float(hy));
    __nv_bfloat162 q1 = __floats2bfloat162_rn(v.z - __bfloat162float(hz),
                                              v.w - __bfloat162float(hw));
    lop.x = *reinterpret_cast<unsigned*>(&q0);
    lop.y = *reinterpret_cast<unsigned*>(&q1);
}

__device__ __forceinline__ float sigf(float x) {
    return __fdividef(1.0f, 1.0f + __expf(-x));
}
__device__ __forceinline__ float tanhfast(float x) {
    return __fdividef(2.0f, 1.0f + __expf(-2.0f * x)) - 1.0f;
}

// ================= split pass =================
__global__ __launch_bounds__(256) void split_inputs(
    const float* __restrict__ x,
    const float* __restrict__ wih,
    const float* __restrict__ h0)
{
    if (blockIdx.x == 0 && threadIdx.x < NBLK) g_flags[threadIdx.x] = 0;

    const size_t NX  = (size_t)T_STEPS * BATCH * INDIM / 4;
    const size_t NW  = (size_t)G4 * INDIM / 4;
    const size_t NH0 = (size_t)BATCH * HID / 4;
    const size_t total = NX + NW + NH0;
    for (size_t i = (size_t)blockIdx.x * blockDim.x + threadIdx.x;
         i < total; i += (size_t)gridDim.x * blockDim.x) {
        if (i < NX) {
            float4 v = ((const float4*)x)[i];
            uint2 h, l; split4(v, h, l);
            ((uint2*)g_xhi)[i] = h;
            ((uint2*)g_xlo)[i] = l;
        } else if (i < NX + NW) {
            size_t k = i - NX;
            float4 v = ((const float4*)wih)[k];
            uint2 h, l; split4(v, h, l);
            ((uint2*)g_wihhi)[k] = h;
            ((uint2*)g_wihlo)[k] = l;
        } else {
            size_t e4 = i - NX - NW;
            size_t e  = e4 * 4;
            int b = (int)(e >> 10);
            int kbase = (int)(e & 1023);
            float4 v = ((const float4*)h0)[e4];
            float vv[4] = {v.x, v.y, v.z, v.w};
            int r  = b & 15;
            int rb = b >> 4;
#pragma unroll
            for (int q = 0; q < 4; q++) {
                int k  = kbase + q;
                int kg = k >> 4, kk = k & 15;
                int lanep = ((r & 7) << 2) + ((kk & 7) >> 1);
                int reg   = ((kk >= 8) ? 2 : 0) + ((r >= 8) ? 1 : 0);
                int byte_ = kk & 1;
                __nv_bfloat16 hi = __float2bfloat16_rn(vv[q]);
                __nv_bfloat16 lo = __float2bfloat16_rn(vv[q] - __bfloat162float(hi));
                ((__nv_bfloat16*)&g_hpk[0][0][rb][kg][lanep])[reg * 2 + byte_] = hi;
                ((__nv_bfloat16*)&g_hpk[0][1][rb][kg][lanep])[reg * 2 + byte_] = lo;
            }
        }
    }
}

// ================= x_proj GEMM (chain-separated bf16-split HMMA) =================
#define XP_ROWB 144
#define XP_TILE (128 * XP_ROWB)
#define XP_BUF  (4 * XP_TILE)
#define XP_SMEM (2 * XP_BUF)

__global__ __launch_bounds__(256) void xproj_mma(
    const float* __restrict__ bih,
    const float* __restrict__ bhh)
{
    extern __shared__ char smem[];
    const uint32_t sb = smem_u32(smem);
    const int tid  = threadIdx.x;
    const int lane = tid & 31;
    const int w    = tid >> 5;
    const int wm   = w & 1;
    const int wn   = w >> 1;
    const int jb   = blockIdx.x * 32;
    const size_t mb = (size_t)blockIdx.y * 128;

    float acc[4][4][4];
#pragma unroll
    for (int a = 0; a < 4; a++)
#pragma unroll
        for (int b = 0; b < 4; b++)
#pragma unroll
            for (int c = 0; c < 4; c++) acc[a][b][c] = 0.f;

    const int a_row = wm * 64 + (lane & 7) + ((lane >> 3) & 1) * 8;
    const int a_k8  = (lane >> 4) * 8;
    const int b_row = wn * 32 + (lane & 7) + (lane >> 4) * 8;
    const int b_k8  = ((lane >> 3) & 1) * 8;

    int st_row[4], st_c[4], st_wrow[4];
#pragma unroll
    for (int q = 0; q < 4; q++) {
        int s = tid * 4 + q;
        st_row[q]  = s >> 3;
        st_c[q]    = s & 7;
        st_wrow[q] = (st_row[q] & 3) * HID + jb + (st_row[q] >> 2);
    }

    auto stage = [&](int kb, int buf) {
        uint32_t base = sb + buf * XP_BUF;
#pragma unroll
        for (int q = 0; q < 4; q++) {
            size_t gk = (size_t)kb * 64 + st_c[q] * 8;
            uint32_t off = st_row[q] * XP_ROWB + st_c[q] * 16;
            cp16(base + 0 * XP_TILE + off, &g_xhi[(mb + st_row[q]) * INDIM + gk]);
            cp16(base + 1 * XP_TILE + off, &g_xlo[(mb + st_row[q]) * INDIM + gk]);
            cp16(base + 2 * XP_TILE + off, &g_wihhi[(size_t)st_wrow[q] * INDIM + gk]);
            cp16(base + 3 * XP_TILE + off, &g_wihlo[(size_t)st_wrow[q] * INDIM + gk]);
        }
        CP_COMMIT();
    };

    stage(0, 0);

    for (int kb = 0; kb < 8; kb++) {
        const int buf = kb & 1;
        if (kb < 7) stage(kb + 1, buf ^ 1);
        if (kb < 7) { CP_WAIT(1); } else { CP_WAIT(0); }
        __syncthreads();

        const uint32_t aHi = sb + buf * XP_BUF;
        const uint32_t aLo = aHi + XP_TILE;
        const uint32_t bHi = aHi + 2 * XP_TILE;
        const uint32_t bLo = aHi + 3 * XP_TILE;

#pragma unroll
        for (int s = 0; s < 4; s++) {
            uint32_t bh[8], bl[8];
#pragma unroll
            for (int p = 0; p < 2; p++) {
                uint32_t off = (b_row + p * 16) * XP_ROWB + (s * 16 + b_k8) * 2;
                LDSM_X4(bh[p*4+0], bh[p*4+1], bh[p*4+2], bh[p*4+3], bHi + off);
                LDSM_X4(bl[p*4+0], bl[p*4+1], bl[p*4+2], bl[p*4+3], bLo + off);
            }
            // process m-tiles in pairs; 3 separated passes (chain distance 8 MMAs)
#pragma unroll
            for (int mp = 0; mp < 2; mp++) {
                uint32_t ah[2][4], al[2][4];
#pragma unroll
                for (int mi = 0; mi < 2; mi++) {
                    int mt = mp * 2 + mi;
                    uint32_t off = (a_row + mt * 16) * XP_ROWB + (s * 16 + a_k8) * 2;
                    LDSM_X4(ah[mi][0], ah[mi][1], ah[mi][2], ah[mi][3], aHi + off);
                    LDSM_X4(al[mi][0], al[mi][1], al[mi][2], al[mi][3], aLo + off);
                }
                // pass 1: hi * Whi
#pragma unroll
                for (int mi = 0; mi < 2; mi++)
#pragma unroll
                    for (int nt = 0; nt < 4; nt++) {
                        float* d = acc[mp * 2 + mi][nt];
                        mma_bf16(d[0], d[1], d[2], d[3],
                                 ah[mi][0], ah[mi][1], ah[mi][2], ah[mi][3],
                                 bh[nt*2], bh[nt*2+1]);
                    }
                // pass 2: hi * Wlo
#pragma unroll
                for (int mi = 0; mi < 2; mi++)
#pragma unroll
                    for (int nt = 0; nt < 4; nt++) {
                        float* d = acc[mp * 2 + mi][nt];
                        mma_bf16(d[0], d[1], d[2], d[3],
                                 ah[mi][0], ah[mi][1], ah[mi][2], ah[mi][3],
                                 bl[nt*2], bl[nt*2+1]);
                    }
                // pass 3: lo * Whi
#pragma unroll
                for (int mi = 0; mi < 2; mi++)
#pragma unroll
                    for (int nt = 0; nt < 4; nt++) {
                        float* d = acc[mp * 2 + mi][nt];
                        mma_bf16(d[0], d[1], d[2], d[3],
                                 al[mi][0], al[mi][1], al[mi][2], al[mi][3],
                                 bh[nt*2], bh[nt*2+1]);
                    }
            }
        }
        __syncthreads();
    }

    const int colq = (lane & 3) * 2;
#pragma unroll
    for (int nt = 0; nt < 4; nt++) {
        int nloc = wn * 32 + nt * 8 + colq;
        int g0 = nloc & 3,        j0 = jb + (nloc >> 2);
        int g1 = (nloc + 1) & 3,  j1 = jb + ((nloc + 1) >> 2);
        float bb0 = bih[g0 * HID + j0] + bhh[g0 * HID + j0];
        float bb1 = bih[g1 * HID + j1] + bhh[g1 * HID + j1];
#pragma unroll
        for (int mt = 0; mt < 4; mt++) {
            size_t r0 = mb + wm * 64 + mt * 16 + (lane >> 2);
            float2 v0 = make_float2(acc[mt][nt][0] + bb0, acc[mt][nt][1] + bb1);
            float2 v1 = make_float2(acc[mt][nt][2] + bb0, acc[mt][nt][3] + bb1);
            *(float2*)&g_xproj[r0 * G4 + jb * 4 + nloc]       = v0;
            *(float2*)&g_xproj[(r0 + 8) * G4 + jb * 4 + nloc] = v1;
        }
    }
}

// ================= persistent recurrent kernel (M2xK4, fence-free barrier) =================
__global__ __launch_bounds__(256, 1) void lstm_rec_pk(
    const float* __restrict__ c0in,
    const float* __restrict__ whh,
    float* __restrict__ out, int out_size)
{
    extern __shared__ char smem[];
    const uint32_t sb = smem_u32(smem);
    const int tid  = threadIdx.x;
    const int lane = tid & 31;
    const int w    = tid >> 5;
    const int mtp  = w & 1;            // m pair
    const int ks   = w >> 1;           // K quarter
    const int blk  = blockIdx.x;
    const int hb   = blk * 8;
    const int kgc  = blk >> 1;

    // one-time: W slice -> smem (gate-interleaved rows, proven mapping), hi+lo
    for (int it = 0; it < 32; it++) {
        int e4 = it * 256 + tid;
        int n  = e4 >> 8;
        int kf = (e4 & 255) * 4;
        int nh_ = n >> 4, r = n & 15;
        int nt = r >> 3, q = (r & 7) >> 1, low = r & 1;
        int gate = nt * 2 + low, j = 4 * nh_ + q;
        float4 v = *(const float4*)&whh[(size_t)(gate * HID + hb + j) * HID + kf];
        uint2 hp, lp; split4(v, hp, lp);
        *(uint2*)(smem + SM_W + n * WROWB + kf * 2) = hp;
        *(uint2*)(smem + SM_W + WPLANE + n * WROWB + kf * 2) = lp;
    }
    __syncthreads();

    const uint32_t bRow0 = (uint32_t)((lane & 7) + ((lane >> 4) << 3)) * WROWB;
    const uint32_t bRow1 = bRow0 + 16u * WROWB;
    const uint32_t bK8   = ((lane >> 3) & 1) * 8;

    const int j0 = lane & 3;
    const int j1 = 4 + j0;
    const int col0 = hb + j0;
    const int col1 = hb + j1;

    // cell role: warps ks<2 handle mt = 2*mtp + ks
    const int cmt = 2 * mtp + ks;                 // valid when ks<2
    const int cb0 = cmt * 16 + (lane >> 2);
    const int cb1 = cb0 + 8;
    const uint32_t off0 = (uint32_t)(cmt * 32 + ((lane >> 2) << 2) + (j0 >> 1)) * 8 + (j0 & 1) * 2;
    const uint32_t off1 = (uint32_t)(cmt * 32 + ((lane >> 2) << 2) + (j1 >> 1)) * 8 + (j1 & 1) * 2;

    float cst[4] = {0.f, 0.f, 0.f, 0.f};
    float4 xg0, xg1, xg2, xg3;
    if (ks < 2) {
        cst[0] = c0in[cb0 * HID + col0];
        cst[1] = c0in[cb1 * HID + col0];
        cst[2] = c0in[cb0 * HID + col1];
        cst[3] = c0in[cb1 * HID + col1];
        // xg for t = 0
        const float* xpb = g_xproj;
        xg0 = *(const float4*)(xpb + (size_t)cb0 * G4 + col0 * 4);
        xg1 = *(const float4*)(xpb + (size_t)cb1 * G4 + col0 * 4);
        xg2 = *(const float4*)(xpb + (size_t)cb0 * G4 + col1 * 4);
        xg3 = *(const float4*)(xpb + (size_t)cb1 * G4 + col1 * 4);
    }

    float4* red = (float4*)(smem + SM_RED);   // [src(3)][mtp(2)][mti(2)][tt(4)][lane]

    for (int t = 0; t < T_STEPS; t++) {
        const int rbuf = t & 1;
        const uint4* __restrict__ Ahp[2];
        const uint4* __restrict__ Alp[2];
#pragma unroll
        for (int mti = 0; mti < 2; mti++) {
            Ahp[mti] = &g_hpk[rbuf][0][2 * mtp + mti][ks * 16][lane];
            Alp[mti] = &g_hpk[rbuf][1][2 * mtp + mti][ks * 16][lane];
        }

        // 6-deep A prefetch per m-tile (24 outstanding uint4/thread)
        uint4 pah[6][2], pal[6][2];
#pragma unroll
        for (int i = 0; i < 6; i++)
#pragma unroll
            for (int mti = 0; mti < 2; mti++) {
                pah[i][mti] = __ldcg(&Ahp[mti][i * 32]);
                pal[i][mti] = __ldcg(&Alp[mti][i * 32]);
            }

        float am[2][4][4], ac[2][4][4];
#pragma unroll
        for (int mti = 0; mti < 2; mti++)
#pragma unroll
            for (int tt = 0; tt < 4; tt++)
#pragma unroll
                for (int c = 0; c < 4; c++) { am[mti][tt][c] = 0.f; ac[mti][tt][c] = 0.f; }

#pragma unroll
        for (int kg = 0; kg < 16; kg++) {
            const int slot = kg % 6;
            uint4 vh[2], vl[2];
#pragma unroll
            for (int mti = 0; mti < 2; mti++) { vh[mti] = pah[slot][mti]; vl[mti] = pal[slot][mti]; }
            if (kg + 6 < 16) {
#pragma unroll
                for (int mti = 0; mti < 2; mti++) {
                    pah[slot][mti] = __ldcg(&Ahp[mti][(kg + 6) * 32]);
                    pal[slot][mti] = __ldcg(&Alp[mti][(kg + 6) * 32]);
                }
            }
            const int kgg = ks * 16 + kg;
            const uint32_t ko = (uint32_t)((kgg * 16 + bK8) << 1);
            uint32_t bh[8], bl[8];
            LDSM_X4(bh[0], bh[1], bh[2], bh[3], sb + SM_W + bRow0 + ko);
            LDSM_X4(bh[4], bh[5], bh[6], bh[7], sb + SM_W + bRow1 + ko);
            LDSM_X4(bl[0], bl[1], bl[2], bl[3], sb + SM_W + WPLANE + bRow0 + ko);
            LDSM_X4(bl[4], bl[5], bl[6], bl[7], sb + SM_W + WPLANE + bRow1 + ko);
            // pass 1: hi * Whi (main)
#pragma unroll
            for (int mti = 0; mti < 2; mti++)
#pragma unroll
                for (int tt = 0; tt < 4; tt++)
                    mma_bf16(am[mti][tt][0], am[mti][tt][1], am[mti][tt][2], am[mti][tt][3],
                             vh[mti].x, vh[mti].y, vh[mti].z, vh[mti].w, bh[tt*2], bh[tt*2+1]);
            // pass 2: hi * Wlo
#pragma unroll
            for (int mti = 0; mti < 2; mti++)
#pragma unroll
                for (int tt = 0; tt < 4; tt++)
                    mma_bf16(ac[mti][tt][0], ac[mti][tt][1], ac[mti][tt][2], ac[mti][tt][3],
                             vh[mti].x, vh[mti].y, vh[mti].z, vh[mti].w, bl[tt*2], bl[tt*2+1]);
            // pass 3: lo * Whi
#pragma unroll
            for (int mti = 0; mti < 2; mti++)
#pragma unroll
                for (int tt = 0; tt < 4; tt++)
                    mma_bf16(ac[mti][tt][0], ac[mti][tt][1], ac[mti][tt][2], ac[mti][tt][3],
                             vl[mti].x, vl[mti].y, vl[mti].z, vl[mti].w, bh[tt*2], bh[tt*2+1]);
        }

        // chain sums into am
#pragma unroll
        for (int mti = 0; mti < 2; mti++)
#pragma unroll
            for (int tt = 0; tt < 4; tt++)
#pragma unroll
                for (int c = 0; c < 4; c++) am[mti][tt][c] += ac[mti][tt][c];

        // write partials for mti's handled by other cell warps
        {
            const int src = (ks < 2) ? 0 : ks - 1;
#pragma unroll
            for (int mti = 0; mti < 2; mti++) {
                if (ks != mti) {
                    int base = ((src * 2 + mtp) * 2 + mti) * 4;
#pragma unroll
                    for (int tt = 0; tt < 4; tt++)
                        red[(base + tt) * 32 + lane] =
                            make_float4(am[mti][tt][0], am[mti][tt][1],
                                        am[mti][tt][2], am[mti][tt][3]);
                }
            }
        }
        __syncthreads();

        float hvv[4];
        if (ks < 2) {
            const int mti = ks;
#pragma unroll
            for (int src = 0; src < 3; src++) {
                int base = ((src * 2 + mtp) * 2 + mti) * 4;
#pragma unroll
                for (int tt = 0; tt < 4; tt++) {
                    float4 v = red[(base + tt) * 32 + lane];
                    am[mti][tt][0] += v.x; am[mti][tt][1] += v.y;
                    am[mti][tt][2] += v.z; am[mti][tt][3] += v.w;
                }
            }
            float (*G)[4] = am[mti];
            float ig, fg, gg, og;
            ig = sigf(G[0][0] + xg0.x); fg = sigf(G[0][1] + xg0.y);
            gg = tanhfast(G[1][0] + xg0.z); og = sigf(G[1][1] + xg0.w);
            cst[0] = fg * cst[0] + ig * gg;  hvv[0] = og * tanhfast(cst[0]);

            ig = sigf(G[0][2] + xg1.x); fg = sigf(G[0][3] + xg1.y);
            gg = tanhfast(G[1][2] + xg1.z); og = sigf(G[1][3] + xg1.w);
            cst[1] = fg * cst[1] + ig * gg;  hvv[1] = og * tanhfast(cst[1]);

            ig = sigf(G[2][0] + xg2.x); fg = sigf(G[2][1] + xg2.y);
            gg = tanhfast(G[3][0] + xg2.z); og = sigf(G[3][1] + xg2.w);
            cst[2] = fg * cst[2] + ig * gg;  hvv[2] = og * tanhfast(cst[2]);

            ig = sigf(G[2][2] + xg3.x); fg = sigf(G[2][3] + xg3.y);
            gg = tanhfast(G[3][2] + xg3.z); og = sigf(G[3][3] + xg3.w);
            cst[3] = fg * cst[3] + ig * gg;  hvv[3] = og * tanhfast(cst[3]);

            // stage packed-h slice
            char* st = smem + SM_STAGE;
            __nv_bfloat16 h0 = __float2bfloat16_rn(hvv[0]);
            __nv_bfloat16 h1 = __float2bfloat16_rn(hvv[1]);
            __nv_bfloat16 h2 = __float2bfloat16_rn(hvv[2]);
            __nv_bfloat16 h3 = __float2bfloat16_rn(hvv[3]);
            *(__nv_bfloat16*)(st + off0)        = h0;
            *(__nv_bfloat16*)(st + off0 + 4)    = h1;
            *(__nv_bfloat16*)(st + off1)        = h2;
            *(__nv_bfloat16*)(st + off1 + 4)    = h3;
            *(__nv_bfloat16*)(st + off0 + 1024) = __float2bfloat16_rn(hvv[0] - __bfloat162float(h0));
            *(__nv_bfloat16*)(st + off0 + 1028) = __float2bfloat16_rn(hvv[1] - __bfloat162float(h1));
            *(__nv_bfloat16*)(st + off1 + 1024) = __float2bfloat16_rn(hvv[2] - __bfloat162float(h2));
            *(__nv_bfloat16*)(st + off1 + 1028) = __float2bfloat16_rn(hvv[3] - __bfloat162float(h3));
        }
        __syncthreads();

        // coalesced packed writeback: 256 threads, one STG.64 each
        {
            const int wbuf = (t + 1) & 1;
            int plane = tid >> 7, rb = (tid >> 5) & 3, lt = tid & 31;
            uint2 v = *(uint2*)(smem + SM_STAGE + (uint32_t)((plane * 4 + rb) * 32 + lt) * 8);
            uint2* dst = (uint2*)&g_hpk[wbuf][plane][rb][kgc][lt];
            dst[blk & 1] = v;
        }

        if (t == T_STEPS - 1) {
            if (ks < 2) {
                out[((size_t)t * BATCH + cb0) * HID + col0] = hvv[0];
                out[((size_t)t * BATCH + cb1) * HID + col0] = hvv[1];
                out[((size_t)t * BATCH + cb0) * HID + col1] = hvv[2];
                out[((size_t)t * BATCH + cb1) * HID + col1] = hvv[3];
                const long long need = (long long)T_STEPS * BATCH * HID + 2LL * BATCH * HID;
                if ((long long)out_size >= need) {
                    size_t base = (size_t)T_STEPS * BATCH * HID;
                    out[base + (size_t)cb0 * HID + col0] = hvv[0];
                    out[base + (size_t)cb1 * HID + col0] = hvv[1];
                    out[base + (size_t)cb0 * HID + col1] = hvv[2];
                    out[base + (size_t)cb1 * HID + col1] = hvv[3];
                    size_t cb = base + (size_t)BATCH * HID;
                    out[cb + (size_t)cb0 * HID + col0] = cst[0];
                    out[cb + (size_t)cb1 * HID + col0] = cst[1];
                    out[cb + (size_t)cb0 * HID + col1] = cst[2];
                    out[cb + (size_t)cb1 * HID + col1] = cst[3];
                }
            }
        } else {
            // fence-free barrier: writeback STGs -> bar -> release flag;
            // acquire-poll on the consumer side. No MEMBAR.ALL / CCTL.IVALL.
            __syncthreads();
            if (tid == 0) st_rel(&g_flags[blk], t + 1);
            if (ks < 2) {
                // out stores + next-step xg prefetch off the critical path
                out[((size_t)t * BATCH + cb0) * HID + col0] = hvv[0];
                out[((size_t)t * BATCH + cb1) * HID + col0] = hvv[1];
                out[((size_t)t * BATCH + cb0) * HID + col1] = hvv[2];
                out[((size_t)t * BATCH + cb1) * HID + col1] = hvv[3];
                const float* xpb = g_xproj + ((size_t)(t + 1) * BATCH) * G4;
                xg0 = *(const float4*)(xpb + (size_t)cb0 * G4 + col0 * 4);
                xg1 = *(const float4*)(xpb + (size_t)cb1 * G4 + col0 * 4);
                xg2 = *(const float4*)(xpb + (size_t)cb0 * G4 + col1 * 4);
                xg3 = *(const float4*)(xpb + (size_t)cb1 * G4 + col1 * 4);
            }
            if (tid < NBLK) {
                while (ld_acq(&g_flags[tid]) < t + 1) { __nanosleep(32); }
            }
            __syncthreads();
        }
    }
}

// ================= launch =================
extern "C" void kernel_launch(void* const* d_in, const int* in_sizes, int n_in,
                              void* d_out, int out_size) {
    const float* x    = (const float*)d_in[0];
    const float* h0   = (const float*)d_in[1];
    const float* c0   = (const float*)d_in[2];
    const float* w_ih = (const float*)d_in[3];
    const float* w_hh = (const float*)d_in[4];
    const float* b_ih = (const float*)d_in[5];
    const float* b_hh = (const float*)d_in[6];
    float* out = (float*)d_out;

    cudaFuncSetAttribute(xproj_mma,
                         cudaFuncAttributeMaxDynamicSharedMemorySize, XP_SMEM);
    cudaFuncSetAttribute(lstm_rec_pk,
                         cudaFuncAttributeMaxDynamicSharedMemorySize, R_SMEM);

    split_inputs<<<2048, 256>>>(x, w_ih, h0);
    dim3 gx(G4 / 128, (T_STEPS * BATCH) / 128);   // 32 x 512
    xproj_mma<<<gx, 256, XP_SMEM>>>(b_ih, b_hh);
    lstm_rec_pk<<<NBLK, 256, R_SMEM>>>(c0, w_hh, out, out_size);
}